// round 13
// baseline (speedup 1.0000x reference)
#include <cuda_runtime.h>
#include <cuda_fp16.h>
#include <math.h>
#include <stdint.h>

#define BB 16
#define TT 64
#define DD 2304
#define HH 2304
#define GG 9216
#define EE 768
#define LANES 32
#define MAXS 32
#define NSTEPS 31
#define KC 144            // K chunks of 16 (2304/16)
#define NTH 144           // step tiles: 16 j x 4 gates = 64 rows each
#define NXB 144           // W_ih blocks of 64 gate rows
#define KH8 18            // kc chunks per k-split octant (144/8)

// ---------------- device scratch (no runtime allocation) --------------------
__device__ float g_xp [LANES * MAXS * GG];
__device__ float g_h[LANES * HH];            // final h per lane
__device__ float g_c[LANES * HH];
__device__ int   g_len[LANES];
__device__ int   g_length[BB];
__device__ int   g_maxlen;
__device__ int   g_nrows;
__device__ int   g_rows[1024];
// W_hh single-fp16 A-fragments: [tile(144)][kc(144)][gate(4)][T*4+a]  (u32 = 2 half)
__device__ uint32_t g_whh[NTH * KC * 4 * 128];
// W_ih single-fp16 B-fragments: [nblk(144)][kc(144)][T(32)][nt(8)*2+b]
__device__ uint32_t g_wih[NXB * KC * 32 * 16];
// seq rows fp16 hi/lo in A-fragment order: [mtile(16)][kc(144)][w4(4)][T*4+a]
__device__ uint32_t g_a_hi[16 * KC * 4 * 128], g_a_lo[16 * KC * 4 * 128];
// h fp16 hi/lo in B-fragment order, double buffered: [kc(144)][T(32)][nt(4)*2+b]
__device__ uint32_t g_hBhi[2][KC * 32 * 8], g_hBlo[2][KC * 32 * 8];

// ---------------- helpers ---------------------------------------------------
// fp16 pack (x -> low half)
__device__ __forceinline__ uint32_t packf16(float x, float y) {
    uint32_t h;
    asm("cvt.rn.f16x2.f32 %0, %1, %2;" : "=r"(h) : "f"(y), "f"(x));
    return h;
}
// fp16: split fp32 pair into packed f16x2 hi and lo
__device__ __forceinline__ void split2h(float x, float y, uint32_t& hi2, uint32_t& lo2) {
    uint32_t h = packf16(x, y);
    __half2 hh = *(__half2*)&h;
    float fx = __half2float(__low2half(hh));
    float fy = __half2float(__high2half(hh));
    lo2 = packf16(x - fx, y - fy);
    hi2 = h;
}
__device__ __forceinline__ void mma16816h(float* c, const uint32_t* a, const uint32_t* b) {
    asm volatile("mma.sync.aligned.m16n8k16.row.col.f32.f16.f16.f32 "
        "{%0,%1,%2,%3}, {%4,%5,%6,%7}, {%8,%9}, {%0,%1,%2,%3};"
        : "+f"(c[0]), "+f"(c[1]), "+f"(c[2]), "+f"(c[3])
        : "r"(a[0]), "r"(a[1]), "r"(a[2]), "r"(a[3]), "r"(b[0]), "r"(b[1]));
}
__device__ __forceinline__ float sigm(float x) { return 1.f / (1.f + expf(-x)); }

// ---------------------------------------------------------------------------
// Kernel 0a: zero states (parallel)
// ---------------------------------------------------------------------------
__global__ void k_zero() {
    int i = blockIdx.x * blockDim.x + threadIdx.x;
    int n = gridDim.x * blockDim.x;
    for (int p = i; p < LANES * HH; p += n) { g_h[p] = 0.f; g_c[p] = 0.f; }
    for (int p = i; p < KC * 32 * 8; p += n) { g_hBhi[0][p] = 0u; g_hBlo[0][p] = 0u; }
}

// ---------------------------------------------------------------------------
// Kernel 0b: lengths, compact row list
// ---------------------------------------------------------------------------
__global__ void k_prep(const int* __restrict__ mask,
                       const int* __restrict__ start,
                       const int* __restrict__ end) {
    int tid = threadIdx.x;
    __shared__ int s_len[LANES];
    if (tid < BB) {
        int L = 0;
        for (int t = 0; t < TT; t++) L += mask[tid * TT + t];
        g_length[tid] = L;
        int ll = start[tid] - 1; if (ll < 1) ll = 1;
        int rl = L - end[tid];   if (rl < 1) rl = 1;
        s_len[tid] = ll;  s_len[BB + tid] = rl;
        g_len[tid] = ll;  g_len[BB + tid] = rl;
    }
    __syncthreads();
    if (tid == 0) {
        int m = 0, n = 0;
        for (int lane = 0; lane < LANES; lane++) {
            int l = s_len[lane];
            if (l > m) m = l;
            for (int t = 0; t < l; t++) g_rows[n++] = (lane << 5) | t;
        }
        g_maxlen = m;
        g_nrows  = n;
    }
    __syncthreads();
    int nr = g_nrows;
    for (int m = nr + tid; m < 1024; m += blockDim.x) g_rows[m] = 0;
}

// ---------------------------------------------------------------------------
// Kernel 1: W_hh -> single-fp16 A-fragment order, coalesced writes.
// grid (KC, NTH), block 128: warp = gate, thread T writes uint4 (T*4+a)
// ---------------------------------------------------------------------------
__global__ void __launch_bounds__(128) k_whhprep(const float* __restrict__ W) {
    int kc = blockIdx.x, tile = blockIdx.y;
    int tid = threadIdx.x, gate = tid >> 5, T = tid & 31;
    uint32_t hi4[4];
#pragma unroll
    for (int a = 0; a < 4; a++) {
        int jj = (a & 1) * 8 + (T >> 2);
        int kk = (a >> 1) * 8 + (T & 3) * 2;
        int r = gate * HH + tile * 16 + jj;
        float2 v = *(const float2*)(W + (size_t)r * DD + kc * 16 + kk);
        hi4[a] = packf16(v.x, v.y);
    }
    size_t idx = (((size_t)tile * KC + kc) * 4 + gate) * 128 + T * 4;
    *(uint4*)&g_whh[idx] = *(uint4*)hi4;
}

// ---------------------------------------------------------------------------
// Kernel 2: W_ih -> single-fp16 B-fragment order, coalesced writes.
// ---------------------------------------------------------------------------
__global__ void __launch_bounds__(128) k_wihprep(const float* __restrict__ W) {
    int kc = blockIdx.x, nblk = blockIdx.y;
    int tid = threadIdx.x;
    int T = tid >> 2;
    uint32_t hi4[4];
#pragma unroll
    for (int i = 0; i < 4; i++) {
        int r = (tid & 3) * 4 + i;
        int nt = r >> 1, b = r & 1;
        int g = nblk * 64 + nt * 8 + (T >> 2);
        int kk = b * 8 + (T & 3) * 2;
        float2 v = *(const float2*)(W + (size_t)g * DD + kc * 16 + kk);
        hi4[i] = packf16(v.x, v.y);
    }
    size_t idx = ((size_t)nblk * KC + kc) * 512 + tid * 4;
    *(uint4*)&g_wih[idx] = *(uint4*)hi4;
}

// ---------------------------------------------------------------------------
// Kernel 3: fused gather + fp16 hi/lo fragment pack of compact seq rows
// ---------------------------------------------------------------------------
__global__ void k_aprep(const float* __restrict__ feat,
                        const int* __restrict__ start,
                        const int* __restrict__ end) {
    int m = blockIdx.y;
    int p = blockIdx.x * blockDim.x + threadIdx.x;
    int k = p * 2;
    int rc = g_rows[m];
    int lane = rc >> 5, t = rc & 31;
    const float* src = nullptr;
    if (lane < BB) {
        int b = lane;
        if (t + 1 < start[b]) src = feat + ((size_t)b * TT + (t + 1)) * DD;
    } else {
        int b = lane - BB;
        int raw = g_length[b] - end[b];
        if (t < raw) src = feat + ((size_t)b * TT + (end[b] + t)) * DD;
    }
    float2 v = make_float2(0.f, 0.f);
    if (src) v = *(const float2*)(src + k);
    int mtile = m >> 6, w = (m & 63) >> 4, rr = m & 15;
    int kc = k >> 4, kk = k & 15;
    int T = (rr & 7) * 4 + ((kk & 7) >> 1);
    int a = (rr >> 3) + 2 * (kk >> 3);
    uint32_t h2, l2; split2h(v.x, v.y, h2, l2);
    size_t idx = (((size_t)mtile * KC + kc) * 4 + w) * 128 + T * 4 + a;
    g_a_hi[idx] = h2;
    g_a_lo[idx] = l2;
}

// ---------------------------------------------------------------------------
// Kernel 4: xp GEMM, fp16 2-product, CTA tile M128 x N128, 512 thr (16 warps).
// grid (72, 8). (Unchanged from the 844us R10 configuration.)
// ---------------------------------------------------------------------------
__global__ void __launch_bounds__(512) k_xp_mma(const float* __restrict__ b_ih,
                                                const float* __restrict__ b_hh) {
    int nrows = g_nrows;
    int m0 = blockIdx.y * 128;
    if (m0 >= nrows) return;
    int bx = blockIdx.x;
    int tid = threadIdx.x, w = tid >> 5, T = tid & 31;
    int mw = w >> 2, nw = w & 3;

    __shared__ int soff[128];
    if (tid < 128) {
        int rc = g_rows[m0 + tid];
        soff[tid] = ((rc >> 5) * MAXS + (rc & 31)) * GG;
    }
    __syncthreads();

    const uint4* Ah[2]; const uint4* Al[2];
#pragma unroll
    for (int mt = 0; mt < 2; mt++) {
        int g16 = mw * 2 + mt;
        int mtile = blockIdx.y * 2 + (g16 >> 2);
        int w4 = g16 & 3;
        Ah[mt] = (const uint4*)g_a_hi + (((size_t)mtile * KC) * 4 + w4) * 32 + T;
        Al[mt] = (const uint4*)g_a_lo + (((size_t)mtile * KC) * 4 + w4) * 32 + T;
    }
    int nblk = bx * 2 + (nw >> 1);
    const uint4* Bp = (const uint4*)g_wih + (((size_t)nblk * KC) * 32 + T) * 4 + (nw & 1) * 2;

    float acc[2][4][4];
#pragma unroll
    for (int mt = 0; mt < 2; mt++)
#pragma unroll
        for (int nt = 0; nt < 4; nt++)
#pragma unroll
            for (int r = 0; r < 4; r++) acc[mt][nt][r] = 0.f;

    uint4 ah[2][2], al[2][2], bp[2][2];
#pragma unroll
    for (int mt = 0; mt < 2; mt++) { ah[0][mt] = Ah[mt][0]; al[0][mt] = Al[mt][0]; }
    bp[0][0] = Bp[0]; bp[0][1] = Bp[1];

    for (int kc = 0; kc < KC; kc++) {
        int cur = kc & 1, nxt = cur ^ 1;
        if (kc + 1 < KC) {
            size_t o = (size_t)(kc + 1) * 128;
#pragma unroll
            for (int mt = 0; mt < 2; mt++) { ah[nxt][mt] = Ah[mt][o]; al[nxt][mt] = Al[mt][o]; }
            bp[nxt][0] = Bp[o]; bp[nxt][1] = Bp[o + 1];
        }
        const uint32_t* Br = (const uint32_t*)&bp[cur][0];
#pragma unroll
        for (int mt = 0; mt < 2; mt++) {
            const uint32_t* Ahr = (const uint32_t*)&ah[cur][mt];
            const uint32_t* Alr = (const uint32_t*)&al[cur][mt];
#pragma unroll
            for (int nt = 0; nt < 4; nt++) {
                mma16816h(acc[mt][nt], Ahr, Br + nt * 2);
                mma16816h(acc[mt][nt], Alr, Br + nt * 2);
            }
        }
    }

#pragma unroll
    for (int mt = 0; mt < 2; mt++)
#pragma unroll
        for (int nt = 0; nt < 4; nt++)
#pragma unroll
            for (int r = 0; r < 4; r++) {
                int g16 = mw * 2 + mt;
                int ml = g16 * 16 + (T >> 2) + 8 * (r >> 1);
                if (m0 + ml < nrows) {
                    int col = bx * 128 + (nw * 4 + nt) * 8 + 2 * (T & 3) + (r & 1);
                    g_xp[(size_t)soff[ml] + col] = acc[mt][nt][r] + b_ih[col] + b_hh[col];
                }
            }
}

// ---------------------------------------------------------------------------
// Kernel 5: one LSTM step via fp16 mma.sync, A single + B hi/lo (2 products).
// grid 144, block 1024 (32 warps = 8/SMSP). warp = gate (w&3) x k-octant
// (w>>2, 18 kc each). Two-phase reduction into 4 SMEM partial buffers.
// ---------------------------------------------------------------------------
__global__ void __launch_bounds__(1024) k_step_mma(int t) {
    if (t >= g_maxlen) return;
    int tile = blockIdx.x;
    int tid = threadIdx.x, w = tid >> 5, T = tid & 31;
    int gate = w & 3, kh = w >> 2;          // kh 0..7
    int rb = t & 1, wb = rb ^ 1;

    __shared__ float gsm[4][64 * 33];

    const uint4* Ap = (const uint4*)g_whh + (((size_t)tile * KC + kh * KH8) * 4 + gate) * 32 + T;
    const uint4* Bh = (const uint4*)g_hBhi[rb] + (size_t)kh * KH8 * 64 + T * 2;
    const uint4* Bl = (const uint4*)g_hBlo[rb] + (size_t)kh * KH8 * 64 + T * 2;

    float acc[4][4];
#pragma unroll
    for (int i = 0; i < 4; i++)
#pragma unroll
        for (int r = 0; r < 4; r++) acc[i][r] = 0.f;

    uint4 ah[2], bh[2][2], bl[2][2];
    ah[0] = Ap[0];
    bh[0][0] = Bh[0]; bh[0][1] = Bh[1];
    bl[0][0] = Bl[0]; bl[0][1] = Bl[1];

    for (int i = 0; i < KH8; i++) {
        int cur = i & 1, nxt = cur ^ 1;
        if (i + 1 < KH8) {
            ah[nxt] = Ap[(size_t)(i + 1) * 128];
            size_t bo = (size_t)(i + 1) * 64;
            bh[nxt][0] = Bh[bo];  bh[nxt][1] = Bh[bo + 1];
            bl[nxt][0] = Bl[bo];  bl[nxt][1] = Bl[bo + 1];
        }
        const uint32_t* Ar  = (const uint32_t*)&ah[cur];
        const uint32_t* Bhr = (const uint32_t*)&bh[cur][0];
        const uint32_t* Blr = (const uint32_t*)&bl[cur][0];
#pragma unroll
        for (int nt = 0; nt < 4; nt++) {
            mma16816h(acc[nt], Ar, Bhr + nt * 2);
            mma16816h(acc[nt], Ar, Blr + nt * 2);
        }
    }

    // two-phase partial reduce into 4 buffers: kh<4 store, then kh>=4 add
    if (kh < 4) {
#pragma unroll
        for (int nt = 0; nt < 4; nt++)
#pragma unroll
            for (int r = 0; r < 4; r++) {
                int rr = (T >> 2) + 8 * (r >> 1);
                int lane = nt * 8 + 2 * (T & 3) + (r & 1);
                gsm[kh][(gate * 16 + rr) * 33 + lane] = acc[nt][r];
            }
    }
    __syncthreads();
    if (kh >= 4) {
#pragma unroll
        for (int nt = 0; nt < 4; nt++)
#pragma unroll
            for (int r = 0; r < 4; r++) {
                int rr = (T >> 2) + 8 * (r >> 1);
                int lane = nt * 8 + 2 * (T & 3) + (r & 1);
                gsm[kh - 4][(gate * 16 + rr) * 33 + lane] += acc[nt][r];
            }
    }
    __syncthreads();

    // pointwise + repack h into fp16 B-fragment layout (256 thr = 32 lanes x 8 jp)
    if (tid < 256) {
        int lane = tid >> 3, jp = tid & 7;
        int jj0 = jp * 2;
        int Tt = (lane & 7) * 4 + ((jj0 & 7) >> 1);
        int nt = lane >> 3, b = jj0 >> 3;
        int idx = tile * 256 + Tt * 8 + nt * 2 + b;
        if (t < g_len[lane]) {
            float hv[2];
            const float* xp = g_xp + ((size_t)(lane * MAXS + t)) * GG;
#pragma unroll
            for (int q = 0; q < 2; q++) {
                int jj = jj0 + q;
                int j = tile * 16 + jj;
                float gi = gsm[0][(0 * 16 + jj) * 33 + lane] + gsm[1][(0 * 16 + jj) * 33 + lane]
                         + gsm[2][(0 * 16 + jj) * 33 + lane] + gsm[3][(0 * 16 + jj) * 33 + lane]
                         + xp[j];
                float gf = gsm[0][(1 * 16 + jj) * 33 + lane] + gsm[1][(1 * 16 + jj) * 33 + lane]
                         + gsm[2][(1 * 16 + jj) * 33 + lane] + gsm[3][(1 * 16 + jj) * 33 + lane]
                         + xp[HH + j];
                float gg = gsm[0][(2 * 16 + jj) * 33 + lane] + gsm[1][(2 * 16 + jj) * 33 + lane]
                         + gsm[2][(2 * 16 + jj) * 33 + lane] + gsm[3][(2 * 16 + jj) * 33 + lane]
                         + xp[2 * HH + j];
                float go = gsm[0][(3 * 16 + jj) * 33 + lane] + gsm[1][(3 * 16 + jj) * 33 + lane]
                         + gsm[2][(3 * 16 + jj) * 33 + lane] + gsm[3][(3 * 16 + jj) * 33 + lane]
                         + xp[3 * HH + j];
                size_t ci = (size_t)lane * HH + j;
                float cc = sigm(gf) * g_c[ci] + sigm(gi) * tanhf(gg);
                g_c[ci] = cc;
                float h = sigm(go) * tanhf(cc);
                g_h[ci] = h;
                hv[q] = h;
            }
            uint32_t h2, l2; split2h(hv[0], hv[1], h2, l2);
            g_hBhi[wb][idx] = h2;
            g_hBlo[wb][idx] = l2;
        } else {
            g_hBhi[wb][idx] = g_hBhi[rb][idx];
            g_hBlo[wb][idx] = g_hBlo[rb][idx];
        }
    }
}

// ---------------------------------------------------------------------------
// Kernel 6: out = [h_left ; h_right] @ W_out^T + b_out
// ---------------------------------------------------------------------------
__global__ void __launch_bounds__(256) k_out(const float* __restrict__ W_out,
                                             const float* __restrict__ b_out,
                                             float* __restrict__ out) {
    int e0 = blockIdx.x * 64;
    int tid = threadIdx.x;
    int eL = tid & 63;
    int bg = tid >> 6;

    __shared__ __align__(16) float Fs[32 * 16];
    __shared__ float Ws[64 * 33];
    float acc[4] = {0.f, 0.f, 0.f, 0.f};

    for (int k0 = 0; k0 < 2 * HH; k0 += 32) {
#pragma unroll
        for (int i = 0; i < 2; i++) {
            int flat = tid + i * 256;
            int b = flat & 15, k = flat >> 4;
            int kk = k0 + k;
            float v = (kk < HH) ? g_h[(size_t)b * HH + kk]
                                : g_h[(size_t)(BB + b) * HH + kk - HH];
            Fs[k * 16 + b] = v;
        }
#pragma unroll
        for (int i = 0; i < 8; i++) {
            int flat = tid + i * 256;
            int e = flat >> 5, k = flat & 31;
            Ws[e * 33 + k] = W_out[(size_t)(e0 + e) * (2 * HH) + k0 + k];
        }
        __syncthreads();
#pragma unroll
        for (int k = 0; k < 32; k++) {
            float wv = Ws[eL * 33 + k];
            float4 f = *(const float4*)&Fs[k * 16 + bg * 4];
            acc[0] += wv * f.x;  acc[1] += wv * f.y;
            acc[2] += wv * f.z;  acc[3] += wv * f.w;
        }
        __syncthreads();
    }
    int e = e0 + eL;
    float bo = b_out[e];
#pragma unroll
    for (int i = 0; i < 4; i++)
        out[(size_t)(bg * 4 + i) * EE + e] = acc[i] + bo;
}

// ---------------------------------------------------------------------------
extern "C" void kernel_launch(void* const* d_in, const int* in_sizes, int n_in,
                              void* d_out, int out_size) {
    const float* feat  = (const float*)d_in[0];
    const int*   mask  = (const int*)  d_in[1];
    const int*   start = (const int*)  d_in[2];
    const int*   end   = (const int*)  d_in[3];
    const float* W_ih  = (const float*)d_in[4];
    const float* W_hh  = (const float*)d_in[5];
    const float* b_ih  = (const float*)d_in[6];
    const float* b_hh  = (const float*)d_in[7];
    const float* W_out = (const float*)d_in[8];
    const float* b_out = (const float*)d_in[9];
    float* out = (float*)d_out;

    k_zero<<<72, 256>>>();
    k_prep<<<1, 512>>>(mask, start, end);
    k_whhprep<<<dim3(KC, NTH), 128>>>(W_hh);
    k_wihprep<<<dim3(KC, NXB), 128>>>(W_ih);
    k_aprep<<<dim3(9, 1024), 128>>>(feat, start, end);
    k_xp_mma<<<dim3(72, 8), 512>>>(b_ih, b_hh);
    for (int t = 0; t < NSTEPS; t++)
        k_step_mma<<<NTH, 1024>>>(t);
    k_out<<<EE / 64, 256>>>(W_out, b_out, out);
}

// round 14
// speedup vs baseline: 1.0069x; 1.0069x over previous
#include <cuda_runtime.h>
#include <cuda_fp16.h>
#include <math.h>
#include <stdint.h>

#define BB 16
#define TT 64
#define DD 2304
#define HH 2304
#define GG 9216
#define EE 768
#define LANES 32
#define MAXS 32
#define NSTEPS 31
#define KC 144            // K chunks of 16 (2304/16)
#define NTH 144           // step tiles: 16 j x 4 gates = 64 rows each
#define NXB 144           // W_ih blocks of 64 gate rows
#define KH8 18            // kc chunks per k-split octant (144/8)

// ---------------- device scratch (no runtime allocation) --------------------
__device__ float g_xp [LANES * MAXS * GG];
__device__ float g_h[LANES * HH];            // final h per lane
__device__ float g_c[LANES * HH];
__device__ int   g_len[LANES];
__device__ int   g_length[BB];
__device__ int   g_maxlen;
__device__ int   g_nrows;
__device__ int   g_rows[1024];
// W_hh single-fp16 A-fragments: [tile(144)][kc(144)][gate(4)][T*4+a]  (u32 = 2 half)
__device__ uint32_t g_whh[NTH * KC * 4 * 128];
// W_ih single-fp16 B-fragments: [nblk(144)][kc(144)][T(32)][nt(8)*2+b]
__device__ uint32_t g_wih[NXB * KC * 32 * 16];
// seq rows fp16 hi/lo in A-fragment order: [mtile(16)][kc(144)][w4(4)][T*4+a]
__device__ uint32_t g_a_hi[16 * KC * 4 * 128], g_a_lo[16 * KC * 4 * 128];
// h fp16 hi/lo in B-fragment order, double buffered: [kc(144)][T(32)][nt(4)*2+b]
__device__ uint32_t g_hBhi[2][KC * 32 * 8], g_hBlo[2][KC * 32 * 8];

// ---------------- helpers ---------------------------------------------------
// fp16 pack (x -> low half)
__device__ __forceinline__ uint32_t packf16(float x, float y) {
    uint32_t h;
    asm("cvt.rn.f16x2.f32 %0, %1, %2;" : "=r"(h) : "f"(y), "f"(x));
    return h;
}
// fp16: split fp32 pair into packed f16x2 hi and lo
__device__ __forceinline__ void split2h(float x, float y, uint32_t& hi2, uint32_t& lo2) {
    uint32_t h = packf16(x, y);
    __half2 hh = *(__half2*)&h;
    float fx = __half2float(__low2half(hh));
    float fy = __half2float(__high2half(hh));
    lo2 = packf16(x - fx, y - fy);
    hi2 = h;
}
__device__ __forceinline__ void mma16816h(float* c, const uint32_t* a, const uint32_t* b) {
    asm volatile("mma.sync.aligned.m16n8k16.row.col.f32.f16.f16.f32 "
        "{%0,%1,%2,%3}, {%4,%5,%6,%7}, {%8,%9}, {%0,%1,%2,%3};"
        : "+f"(c[0]), "+f"(c[1]), "+f"(c[2]), "+f"(c[3])
        : "r"(a[0]), "r"(a[1]), "r"(a[2]), "r"(a[3]), "r"(b[0]), "r"(b[1]));
}
__device__ __forceinline__ float sigm(float x) { return 1.f / (1.f + expf(-x)); }

// ---------------------------------------------------------------------------
// Kernel 0a: zero states (parallel)
// ---------------------------------------------------------------------------
__global__ void k_zero() {
    int i = blockIdx.x * blockDim.x + threadIdx.x;
    int n = gridDim.x * blockDim.x;
    for (int p = i; p < LANES * HH; p += n) { g_h[p] = 0.f; g_c[p] = 0.f; }
    for (int p = i; p < KC * 32 * 8; p += n) { g_hBhi[0][p] = 0u; g_hBlo[0][p] = 0u; }
}

// ---------------------------------------------------------------------------
// Kernel 0b: lengths, compact row list
// ---------------------------------------------------------------------------
__global__ void k_prep(const int* __restrict__ mask,
                       const int* __restrict__ start,
                       const int* __restrict__ end) {
    int tid = threadIdx.x;
    __shared__ int s_len[LANES];
    if (tid < BB) {
        int L = 0;
        for (int t = 0; t < TT; t++) L += mask[tid * TT + t];
        g_length[tid] = L;
        int ll = start[tid] - 1; if (ll < 1) ll = 1;
        int rl = L - end[tid];   if (rl < 1) rl = 1;
        s_len[tid] = ll;  s_len[BB + tid] = rl;
        g_len[tid] = ll;  g_len[BB + tid] = rl;
    }
    __syncthreads();
    if (tid == 0) {
        int m = 0, n = 0;
        for (int lane = 0; lane < LANES; lane++) {
            int l = s_len[lane];
            if (l > m) m = l;
            for (int t = 0; t < l; t++) g_rows[n++] = (lane << 5) | t;
        }
        g_maxlen = m;
        g_nrows  = n;
    }
    __syncthreads();
    int nr = g_nrows;
    for (int m = nr + tid; m < 1024; m += blockDim.x) g_rows[m] = 0;
}

// ---------------------------------------------------------------------------
// Kernel 1: W_hh -> single-fp16 A-fragment order, coalesced writes.
// grid (KC, NTH), block 128: warp = gate, thread T writes uint4 (T*4+a)
// ---------------------------------------------------------------------------
__global__ void __launch_bounds__(128) k_whhprep(const float* __restrict__ W) {
    int kc = blockIdx.x, tile = blockIdx.y;
    int tid = threadIdx.x, gate = tid >> 5, T = tid & 31;
    uint32_t hi4[4];
#pragma unroll
    for (int a = 0; a < 4; a++) {
        int jj = (a & 1) * 8 + (T >> 2);
        int kk = (a >> 1) * 8 + (T & 3) * 2;
        int r = gate * HH + tile * 16 + jj;
        float2 v = *(const float2*)(W + (size_t)r * DD + kc * 16 + kk);
        hi4[a] = packf16(v.x, v.y);
    }
    size_t idx = (((size_t)tile * KC + kc) * 4 + gate) * 128 + T * 4;
    *(uint4*)&g_whh[idx] = *(uint4*)hi4;
}

// ---------------------------------------------------------------------------
// Kernel 2: W_ih -> single-fp16 B-fragment order, coalesced writes.
// ---------------------------------------------------------------------------
__global__ void __launch_bounds__(128) k_wihprep(const float* __restrict__ W) {
    int kc = blockIdx.x, nblk = blockIdx.y;
    int tid = threadIdx.x;
    int T = tid >> 2;
    uint32_t hi4[4];
#pragma unroll
    for (int i = 0; i < 4; i++) {
        int r = (tid & 3) * 4 + i;
        int nt = r >> 1, b = r & 1;
        int g = nblk * 64 + nt * 8 + (T >> 2);
        int kk = b * 8 + (T & 3) * 2;
        float2 v = *(const float2*)(W + (size_t)g * DD + kc * 16 + kk);
        hi4[i] = packf16(v.x, v.y);
    }
    size_t idx = ((size_t)nblk * KC + kc) * 512 + tid * 4;
    *(uint4*)&g_wih[idx] = *(uint4*)hi4;
}

// ---------------------------------------------------------------------------
// Kernel 3: fused gather + fp16 hi/lo fragment pack of compact seq rows
// ---------------------------------------------------------------------------
__global__ void k_aprep(const float* __restrict__ feat,
                        const int* __restrict__ start,
                        const int* __restrict__ end) {
    int m = blockIdx.y;
    int p = blockIdx.x * blockDim.x + threadIdx.x;
    int k = p * 2;
    int rc = g_rows[m];
    int lane = rc >> 5, t = rc & 31;
    const float* src = nullptr;
    if (lane < BB) {
        int b = lane;
        if (t + 1 < start[b]) src = feat + ((size_t)b * TT + (t + 1)) * DD;
    } else {
        int b = lane - BB;
        int raw = g_length[b] - end[b];
        if (t < raw) src = feat + ((size_t)b * TT + (end[b] + t)) * DD;
    }
    float2 v = make_float2(0.f, 0.f);
    if (src) v = *(const float2*)(src + k);
    int mtile = m >> 6, w = (m & 63) >> 4, rr = m & 15;
    int kc = k >> 4, kk = k & 15;
    int T = (rr & 7) * 4 + ((kk & 7) >> 1);
    int a = (rr >> 3) + 2 * (kk >> 3);
    uint32_t h2, l2; split2h(v.x, v.y, h2, l2);
    size_t idx = (((size_t)mtile * KC + kc) * 4 + w) * 128 + T * 4 + a;
    g_a_hi[idx] = h2;
    g_a_lo[idx] = l2;
}

// ---------------------------------------------------------------------------
// Kernel 4: xp GEMM, fp16 2-product, CTA tile M128 x N128, 512 thr (16 warps).
// grid (72, 8). (Unchanged from the 844us R10 configuration.)
// ---------------------------------------------------------------------------
__global__ void __launch_bounds__(512) k_xp_mma(const float* __restrict__ b_ih,
                                                const float* __restrict__ b_hh) {
    int nrows = g_nrows;
    int m0 = blockIdx.y * 128;
    if (m0 >= nrows) return;
    int bx = blockIdx.x;
    int tid = threadIdx.x, w = tid >> 5, T = tid & 31;
    int mw = w >> 2, nw = w & 3;

    __shared__ int soff[128];
    if (tid < 128) {
        int rc = g_rows[m0 + tid];
        soff[tid] = ((rc >> 5) * MAXS + (rc & 31)) * GG;
    }
    __syncthreads();

    const uint4* Ah[2]; const uint4* Al[2];
#pragma unroll
    for (int mt = 0; mt < 2; mt++) {
        int g16 = mw * 2 + mt;
        int mtile = blockIdx.y * 2 + (g16 >> 2);
        int w4 = g16 & 3;
        Ah[mt] = (const uint4*)g_a_hi + (((size_t)mtile * KC) * 4 + w4) * 32 + T;
        Al[mt] = (const uint4*)g_a_lo + (((size_t)mtile * KC) * 4 + w4) * 32 + T;
    }
    int nblk = bx * 2 + (nw >> 1);
    const uint4* Bp = (const uint4*)g_wih + (((size_t)nblk * KC) * 32 + T) * 4 + (nw & 1) * 2;

    float acc[2][4][4];
#pragma unroll
    for (int mt = 0; mt < 2; mt++)
#pragma unroll
        for (int nt = 0; nt < 4; nt++)
#pragma unroll
            for (int r = 0; r < 4; r++) acc[mt][nt][r] = 0.f;

    uint4 ah[2][2], al[2][2], bp[2][2];
#pragma unroll
    for (int mt = 0; mt < 2; mt++) { ah[0][mt] = Ah[mt][0]; al[0][mt] = Al[mt][0]; }
    bp[0][0] = Bp[0]; bp[0][1] = Bp[1];

    for (int kc = 0; kc < KC; kc++) {
        int cur = kc & 1, nxt = cur ^ 1;
        if (kc + 1 < KC) {
            size_t o = (size_t)(kc + 1) * 128;
#pragma unroll
            for (int mt = 0; mt < 2; mt++) { ah[nxt][mt] = Ah[mt][o]; al[nxt][mt] = Al[mt][o]; }
            bp[nxt][0] = Bp[o]; bp[nxt][1] = Bp[o + 1];
        }
        const uint32_t* Br = (const uint32_t*)&bp[cur][0];
#pragma unroll
        for (int mt = 0; mt < 2; mt++) {
            const uint32_t* Ahr = (const uint32_t*)&ah[cur][mt];
            const uint32_t* Alr = (const uint32_t*)&al[cur][mt];
#pragma unroll
            for (int nt = 0; nt < 4; nt++) {
                mma16816h(acc[mt][nt], Ahr, Br + nt * 2);
                mma16816h(acc[mt][nt], Alr, Br + nt * 2);
            }
        }
    }

#pragma unroll
    for (int mt = 0; mt < 2; mt++)
#pragma unroll
        for (int nt = 0; nt < 4; nt++)
#pragma unroll
            for (int r = 0; r < 4; r++) {
                int g16 = mw * 2 + mt;
                int ml = g16 * 16 + (T >> 2) + 8 * (r >> 1);
                if (m0 + ml < nrows) {
                    int col = bx * 128 + (nw * 4 + nt) * 8 + 2 * (T & 3) + (r & 1);
                    g_xp[(size_t)soff[ml] + col] = acc[mt][nt][r] + b_ih[col] + b_hh[col];
                }
            }
}

// ---------------------------------------------------------------------------
// Kernel 5: one LSTM step via fp16 mma.sync, A single + B hi/lo (2 products).
// grid 144, block 1024 (32 warps = 8/SMSP). warp = gate (w&3) x k-octant
// (w>>2, 18 kc each). Two-phase reduction into 4 SMEM partial buffers.
// ---------------------------------------------------------------------------
__global__ void __launch_bounds__(1024) k_step_mma(int t) {
    if (t >= g_maxlen) return;
    int tile = blockIdx.x;
    int tid = threadIdx.x, w = tid >> 5, T = tid & 31;
    int gate = w & 3, kh = w >> 2;          // kh 0..7
    int rb = t & 1, wb = rb ^ 1;

    __shared__ float gsm[4][64 * 33];

    const uint4* Ap = (const uint4*)g_whh + (((size_t)tile * KC + kh * KH8) * 4 + gate) * 32 + T;
    const uint4* Bh = (const uint4*)g_hBhi[rb] + (size_t)kh * KH8 * 64 + T * 2;
    const uint4* Bl = (const uint4*)g_hBlo[rb] + (size_t)kh * KH8 * 64 + T * 2;

    float acc[4][4];
#pragma unroll
    for (int i = 0; i < 4; i++)
#pragma unroll
        for (int r = 0; r < 4; r++) acc[i][r] = 0.f;

    uint4 ah[2], bh[2][2], bl[2][2];
    ah[0] = Ap[0];
    bh[0][0] = Bh[0]; bh[0][1] = Bh[1];
    bl[0][0] = Bl[0]; bl[0][1] = Bl[1];

    for (int i = 0; i < KH8; i++) {
        int cur = i & 1, nxt = cur ^ 1;
        if (i + 1 < KH8) {
            ah[nxt] = Ap[(size_t)(i + 1) * 128];
            size_t bo = (size_t)(i + 1) * 64;
            bh[nxt][0] = Bh[bo];  bh[nxt][1] = Bh[bo + 1];
            bl[nxt][0] = Bl[bo];  bl[nxt][1] = Bl[bo + 1];
        }
        const uint32_t* Ar  = (const uint32_t*)&ah[cur];
        const uint32_t* Bhr = (const uint32_t*)&bh[cur][0];
        const uint32_t* Blr = (const uint32_t*)&bl[cur][0];
#pragma unroll
        for (int nt = 0; nt < 4; nt++) {
            mma16816h(acc[nt], Ar, Bhr + nt * 2);
            mma16816h(acc[nt], Ar, Blr + nt * 2);
        }
    }

    // two-phase partial reduce into 4 buffers: kh<4 store, then kh>=4 add
    if (kh < 4) {
#pragma unroll
        for (int nt = 0; nt < 4; nt++)
#pragma unroll
            for (int r = 0; r < 4; r++) {
                int rr = (T >> 2) + 8 * (r >> 1);
                int lane = nt * 8 + 2 * (T & 3) + (r & 1);
                gsm[kh][(gate * 16 + rr) * 33 + lane] = acc[nt][r];
            }
    }
    __syncthreads();
    if (kh >= 4) {
#pragma unroll
        for (int nt = 0; nt < 4; nt++)
#pragma unroll
            for (int r = 0; r < 4; r++) {
                int rr = (T >> 2) + 8 * (r >> 1);
                int lane = nt * 8 + 2 * (T & 3) + (r & 1);
                gsm[kh - 4][(gate * 16 + rr) * 33 + lane] += acc[nt][r];
            }
    }
    __syncthreads();

    // pointwise + repack h into fp16 B-fragment layout (256 thr = 32 lanes x 8 jp)
    if (tid < 256) {
        int lane = tid >> 3, jp = tid & 7;
        int jj0 = jp * 2;
        int Tt = (lane & 7) * 4 + ((jj0 & 7) >> 1);
        int nt = lane >> 3, b = jj0 >> 3;
        int idx = tile * 256 + Tt * 8 + nt * 2 + b;
        if (t < g_len[lane]) {
            float hv[2];
            const float* xp = g_xp + ((size_t)(lane * MAXS + t)) * GG;
#pragma unroll
            for (int q = 0; q < 2; q++) {
                int jj = jj0 + q;
                int j = tile * 16 + jj;
                float gi = gsm[0][(0 * 16 + jj) * 33 + lane] + gsm[1][(0 * 16 + jj) * 33 + lane]
                         + gsm[2][(0 * 16 + jj) * 33 + lane] + gsm[3][(0 * 16 + jj) * 33 + lane]
                         + xp[j];
                float gf = gsm[0][(1 * 16 + jj) * 33 + lane] + gsm[1][(1 * 16 + jj) * 33 + lane]
                         + gsm[2][(1 * 16 + jj) * 33 + lane] + gsm[3][(1 * 16 + jj) * 33 + lane]
                         + xp[HH + j];
                float gg = gsm[0][(2 * 16 + jj) * 33 + lane] + gsm[1][(2 * 16 + jj) * 33 + lane]
                         + gsm[2][(2 * 16 + jj) * 33 + lane] + gsm[3][(2 * 16 + jj) * 33 + lane]
                         + xp[2 * HH + j];
                float go = gsm[0][(3 * 16 + jj) * 33 + lane] + gsm[1][(3 * 16 + jj) * 33 + lane]
                         + gsm[2][(3 * 16 + jj) * 33 + lane] + gsm[3][(3 * 16 + jj) * 33 + lane]
                         + xp[3 * HH + j];
                size_t ci = (size_t)lane * HH + j;
                float cc = sigm(gf) * g_c[ci] + sigm(gi) * tanhf(gg);
                g_c[ci] = cc;
                float h = sigm(go) * tanhf(cc);
                g_h[ci] = h;
                hv[q] = h;
            }
            uint32_t h2, l2; split2h(hv[0], hv[1], h2, l2);
            g_hBhi[wb][idx] = h2;
            g_hBlo[wb][idx] = l2;
        } else {
            g_hBhi[wb][idx] = g_hBhi[rb][idx];
            g_hBlo[wb][idx] = g_hBlo[rb][idx];
        }
    }
}

// ---------------------------------------------------------------------------
// Kernel 6: out = [h_left ; h_right] @ W_out^T + b_out
// ---------------------------------------------------------------------------
__global__ void __launch_bounds__(256) k_out(const float* __restrict__ W_out,
                                             const float* __restrict__ b_out,
                                             float* __restrict__ out) {
    int e0 = blockIdx.x * 64;
    int tid = threadIdx.x;
    int eL = tid & 63;
    int bg = tid >> 6;

    __shared__ __align__(16) float Fs[32 * 16];
    __shared__ float Ws[64 * 33];
    float acc[4] = {0.f, 0.f, 0.f, 0.f};

    for (int k0 = 0; k0 < 2 * HH; k0 += 32) {
#pragma unroll
        for (int i = 0; i < 2; i++) {
            int flat = tid + i * 256;
            int b = flat & 15, k = flat >> 4;
            int kk = k0 + k;
            float v = (kk < HH) ? g_h[(size_t)b * HH + kk]
                                : g_h[(size_t)(BB + b) * HH + kk - HH];
            Fs[k * 16 + b] = v;
        }
#pragma unroll
        for (int i = 0; i < 8; i++) {
            int flat = tid + i * 256;
            int e = flat >> 5, k = flat & 31;
            Ws[e * 33 + k] = W_out[(size_t)(e0 + e) * (2 * HH) + k0 + k];
        }
        __syncthreads();
#pragma unroll
        for (int k = 0; k < 32; k++) {
            float wv = Ws[eL * 33 + k];
            float4 f = *(const float4*)&Fs[k * 16 + bg * 4];
            acc[0] += wv * f.x;  acc[1] += wv * f.y;
            acc[2] += wv * f.z;  acc[3] += wv * f.w;
        }
        __syncthreads();
    }
    int e = e0 + eL;
    float bo = b_out[e];
#pragma unroll
    for (int i = 0; i < 4; i++)
        out[(size_t)(bg * 4 + i) * EE + e] = acc[i] + bo;
}

// ---------------------------------------------------------------------------
extern "C" void kernel_launch(void* const* d_in, const int* in_sizes, int n_in,
                              void* d_out, int out_size) {
    const float* feat  = (const float*)d_in[0];
    const int*   mask  = (const int*)  d_in[1];
    const int*   start = (const int*)  d_in[2];
    const int*   end   = (const int*)  d_in[3];
    const float* W_ih  = (const float*)d_in[4];
    const float* W_hh  = (const float*)d_in[5];
    const float* b_ih  = (const float*)d_in[6];
    const float* b_hh  = (const float*)d_in[7];
    const float* W_out = (const float*)d_in[8];
    const float* b_out = (const float*)d_in[9];
    float* out = (float*)d_out;

    k_zero<<<72, 256>>>();
    k_prep<<<1, 512>>>(mask, start, end);
    k_whhprep<<<dim3(KC, NTH), 128>>>(W_hh);
    k_wihprep<<<dim3(KC, NXB), 128>>>(W_ih);
    k_aprep<<<dim3(9, 1024), 128>>>(feat, start, end);
    k_xp_mma<<<dim3(72, 8), 512>>>(b_ih, b_hh);
    for (int t = 0; t < NSTEPS; t++)
        k_step_mma<<<NTH, 1024>>>(t);
    k_out<<<EE / 64, 256>>>(W_out, b_out, out);
}

// round 15
// speedup vs baseline: 1.0071x; 1.0003x over previous
#include <cuda_runtime.h>
#include <cuda_fp16.h>
#include <math.h>
#include <stdint.h>

#define BB 16
#define TT 64
#define DD 2304
#define HH 2304
#define GG 9216
#define EE 768
#define LANES 32
#define MAXS 32
#define NSTEPS 31
#define KC 144            // K chunks of 16 (2304/16)
#define NTH 144           // step tiles: 16 j x 4 gates = 64 rows each
#define NXB 144           // W_ih blocks of 64 gate rows
#define KH8 18            // kc chunks per k-split octant (144/8)

// ---------------- device scratch (no runtime allocation) --------------------
__device__ float g_xp [LANES * MAXS * GG];
__device__ float g_h[LANES * HH];            // final h per lane
__device__ float g_c[LANES * HH];
__device__ int   g_len[LANES];
__device__ int   g_length[BB];
__device__ int   g_maxlen;
__device__ int   g_nrows;
__device__ int   g_rows[1024];
// W_hh single-fp16 A-fragments: [tile(144)][kc(144)][gate(4)][T*4+a]  (u32 = 2 half)
__device__ uint32_t g_whh[NTH * KC * 4 * 128];
// W_ih single-fp16 B-fragments: [nblk(144)][kc(144)][T(32)][nt(8)*2+b]
__device__ uint32_t g_wih[NXB * KC * 32 * 16];
// seq rows fp16 hi/lo in A-fragment order: [mtile(16)][kc(144)][w4(4)][T*4+a]
__device__ uint32_t g_a_hi[16 * KC * 4 * 128], g_a_lo[16 * KC * 4 * 128];
// h fp16 hi/lo in B-fragment order, double buffered: [kc(144)][T(32)][nt(4)*2+b]
__device__ uint32_t g_hBhi[2][KC * 32 * 8], g_hBlo[2][KC * 32 * 8];

// ---------------- helpers ---------------------------------------------------
// fp16 pack (x -> low half)
__device__ __forceinline__ uint32_t packf16(float x, float y) {
    uint32_t h;
    asm("cvt.rn.f16x2.f32 %0, %1, %2;" : "=r"(h) : "f"(y), "f"(x));
    return h;
}
// fp16: split fp32 pair into packed f16x2 hi and lo
__device__ __forceinline__ void split2h(float x, float y, uint32_t& hi2, uint32_t& lo2) {
    uint32_t h = packf16(x, y);
    __half2 hh = *(__half2*)&h;
    float fx = __half2float(__low2half(hh));
    float fy = __half2float(__high2half(hh));
    lo2 = packf16(x - fx, y - fy);
    hi2 = h;
}
__device__ __forceinline__ void mma16816h(float* c, const uint32_t* a, const uint32_t* b) {
    asm volatile("mma.sync.aligned.m16n8k16.row.col.f32.f16.f16.f32 "
        "{%0,%1,%2,%3}, {%4,%5,%6,%7}, {%8,%9}, {%0,%1,%2,%3};"
        : "+f"(c[0]), "+f"(c[1]), "+f"(c[2]), "+f"(c[3])
        : "r"(a[0]), "r"(a[1]), "r"(a[2]), "r"(a[3]), "r"(b[0]), "r"(b[1]));
}
__device__ __forceinline__ float sigm(float x) { return 1.f / (1.f + expf(-x)); }

// ---------------------------------------------------------------------------
// Kernel 0a: zero states (parallel)
// ---------------------------------------------------------------------------
__global__ void k_zero() {
    int i = blockIdx.x * blockDim.x + threadIdx.x;
    int n = gridDim.x * blockDim.x;
    for (int p = i; p < LANES * HH; p += n) { g_h[p] = 0.f; g_c[p] = 0.f; }
    for (int p = i; p < KC * 32 * 8; p += n) { g_hBhi[0][p] = 0u; g_hBlo[0][p] = 0u; }
}

// ---------------------------------------------------------------------------
// Kernel 0b: lengths, compact row list
// ---------------------------------------------------------------------------
__global__ void k_prep(const int* __restrict__ mask,
                       const int* __restrict__ start,
                       const int* __restrict__ end) {
    int tid = threadIdx.x;
    __shared__ int s_len[LANES];
    if (tid < BB) {
        int L = 0;
        for (int t = 0; t < TT; t++) L += mask[tid * TT + t];
        g_length[tid] = L;
        int ll = start[tid] - 1; if (ll < 1) ll = 1;
        int rl = L - end[tid];   if (rl < 1) rl = 1;
        s_len[tid] = ll;  s_len[BB + tid] = rl;
        g_len[tid] = ll;  g_len[BB + tid] = rl;
    }
    __syncthreads();
    if (tid == 0) {
        int m = 0, n = 0;
        for (int lane = 0; lane < LANES; lane++) {
            int l = s_len[lane];
            if (l > m) m = l;
            for (int t = 0; t < l; t++) g_rows[n++] = (lane << 5) | t;
        }
        g_maxlen = m;
        g_nrows  = n;
    }
    __syncthreads();
    int nr = g_nrows;
    for (int m = nr + tid; m < 1024; m += blockDim.x) g_rows[m] = 0;
}

// ---------------------------------------------------------------------------
// Kernel 1: W_hh -> single-fp16 A-fragment order, coalesced writes.
// grid (KC, NTH), block 128: warp = gate, thread T writes uint4 (T*4+a)
// ---------------------------------------------------------------------------
__global__ void __launch_bounds__(128) k_whhprep(const float* __restrict__ W) {
    int kc = blockIdx.x, tile = blockIdx.y;
    int tid = threadIdx.x, gate = tid >> 5, T = tid & 31;
    uint32_t hi4[4];
#pragma unroll
    for (int a = 0; a < 4; a++) {
        int jj = (a & 1) * 8 + (T >> 2);
        int kk = (a >> 1) * 8 + (T & 3) * 2;
        int r = gate * HH + tile * 16 + jj;
        float2 v = *(const float2*)(W + (size_t)r * DD + kc * 16 + kk);
        hi4[a] = packf16(v.x, v.y);
    }
    size_t idx = (((size_t)tile * KC + kc) * 4 + gate) * 128 + T * 4;
    *(uint4*)&g_whh[idx] = *(uint4*)hi4;
}

// ---------------------------------------------------------------------------
// Kernel 2: W_ih -> single-fp16 B-fragment order, coalesced writes.
// ---------------------------------------------------------------------------
__global__ void __launch_bounds__(128) k_wihprep(const float* __restrict__ W) {
    int kc = blockIdx.x, nblk = blockIdx.y;
    int tid = threadIdx.x;
    int T = tid >> 2;
    uint32_t hi4[4];
#pragma unroll
    for (int i = 0; i < 4; i++) {
        int r = (tid & 3) * 4 + i;
        int nt = r >> 1, b = r & 1;
        int g = nblk * 64 + nt * 8 + (T >> 2);
        int kk = b * 8 + (T & 3) * 2;
        float2 v = *(const float2*)(W + (size_t)g * DD + kc * 16 + kk);
        hi4[i] = packf16(v.x, v.y);
    }
    size_t idx = ((size_t)nblk * KC + kc) * 512 + tid * 4;
    *(uint4*)&g_wih[idx] = *(uint4*)hi4;
}

// ---------------------------------------------------------------------------
// Kernel 3: fused gather + fp16 hi/lo fragment pack of compact seq rows
// ---------------------------------------------------------------------------
__global__ void k_aprep(const float* __restrict__ feat,
                        const int* __restrict__ start,
                        const int* __restrict__ end) {
    int m = blockIdx.y;
    int p = blockIdx.x * blockDim.x + threadIdx.x;
    int k = p * 2;
    int rc = g_rows[m];
    int lane = rc >> 5, t = rc & 31;
    const float* src = nullptr;
    if (lane < BB) {
        int b = lane;
        if (t + 1 < start[b]) src = feat + ((size_t)b * TT + (t + 1)) * DD;
    } else {
        int b = lane - BB;
        int raw = g_length[b] - end[b];
        if (t < raw) src = feat + ((size_t)b * TT + (end[b] + t)) * DD;
    }
    float2 v = make_float2(0.f, 0.f);
    if (src) v = *(const float2*)(src + k);
    int mtile = m >> 6, w = (m & 63) >> 4, rr = m & 15;
    int kc = k >> 4, kk = k & 15;
    int T = (rr & 7) * 4 + ((kk & 7) >> 1);
    int a = (rr >> 3) + 2 * (kk >> 3);
    uint32_t h2, l2; split2h(v.x, v.y, h2, l2);
    size_t idx = (((size_t)mtile * KC + kc) * 4 + w) * 128 + T * 4 + a;
    g_a_hi[idx] = h2;
    g_a_lo[idx] = l2;
}

// ---------------------------------------------------------------------------
// Kernel 4: xp GEMM, fp16 2-product, CTA tile M128 x N128, 512 thr (16 warps).
// grid (72, 8). (Unchanged from the 844us R10 configuration.)
// ---------------------------------------------------------------------------
__global__ void __launch_bounds__(512) k_xp_mma(const float* __restrict__ b_ih,
                                                const float* __restrict__ b_hh) {
    int nrows = g_nrows;
    int m0 = blockIdx.y * 128;
    if (m0 >= nrows) return;
    int bx = blockIdx.x;
    int tid = threadIdx.x, w = tid >> 5, T = tid & 31;
    int mw = w >> 2, nw = w & 3;

    __shared__ int soff[128];
    if (tid < 128) {
        int rc = g_rows[m0 + tid];
        soff[tid] = ((rc >> 5) * MAXS + (rc & 31)) * GG;
    }
    __syncthreads();

    const uint4* Ah[2]; const uint4* Al[2];
#pragma unroll
    for (int mt = 0; mt < 2; mt++) {
        int g16 = mw * 2 + mt;
        int mtile = blockIdx.y * 2 + (g16 >> 2);
        int w4 = g16 & 3;
        Ah[mt] = (const uint4*)g_a_hi + (((size_t)mtile * KC) * 4 + w4) * 32 + T;
        Al[mt] = (const uint4*)g_a_lo + (((size_t)mtile * KC) * 4 + w4) * 32 + T;
    }
    int nblk = bx * 2 + (nw >> 1);
    const uint4* Bp = (const uint4*)g_wih + (((size_t)nblk * KC) * 32 + T) * 4 + (nw & 1) * 2;

    float acc[2][4][4];
#pragma unroll
    for (int mt = 0; mt < 2; mt++)
#pragma unroll
        for (int nt = 0; nt < 4; nt++)
#pragma unroll
            for (int r = 0; r < 4; r++) acc[mt][nt][r] = 0.f;

    uint4 ah[2][2], al[2][2], bp[2][2];
#pragma unroll
    for (int mt = 0; mt < 2; mt++) { ah[0][mt] = Ah[mt][0]; al[0][mt] = Al[mt][0]; }
    bp[0][0] = Bp[0]; bp[0][1] = Bp[1];

    for (int kc = 0; kc < KC; kc++) {
        int cur = kc & 1, nxt = cur ^ 1;
        if (kc + 1 < KC) {
            size_t o = (size_t)(kc + 1) * 128;
#pragma unroll
            for (int mt = 0; mt < 2; mt++) { ah[nxt][mt] = Ah[mt][o]; al[nxt][mt] = Al[mt][o]; }
            bp[nxt][0] = Bp[o]; bp[nxt][1] = Bp[o + 1];
        }
        const uint32_t* Br = (const uint32_t*)&bp[cur][0];
#pragma unroll
        for (int mt = 0; mt < 2; mt++) {
            const uint32_t* Ahr = (const uint32_t*)&ah[cur][mt];
            const uint32_t* Alr = (const uint32_t*)&al[cur][mt];
#pragma unroll
            for (int nt = 0; nt < 4; nt++) {
                mma16816h(acc[mt][nt], Ahr, Br + nt * 2);
                mma16816h(acc[mt][nt], Alr, Br + nt * 2);
            }
        }
    }

#pragma unroll
    for (int mt = 0; mt < 2; mt++)
#pragma unroll
        for (int nt = 0; nt < 4; nt++)
#pragma unroll
            for (int r = 0; r < 4; r++) {
                int g16 = mw * 2 + mt;
                int ml = g16 * 16 + (T >> 2) + 8 * (r >> 1);
                if (m0 + ml < nrows) {
                    int col = bx * 128 + (nw * 4 + nt) * 8 + 2 * (T & 3) + (r & 1);
                    g_xp[(size_t)soff[ml] + col] = acc[mt][nt][r] + b_ih[col] + b_hh[col];
                }
            }
}

// ---------------------------------------------------------------------------
// Kernel 5: one LSTM step via fp16 mma.sync, A single + B hi/lo (2 products).
// grid 144, block 1024 (32 warps = 8/SMSP). warp = gate (w&3) x k-octant
// (w>>2, 18 kc each). Two-phase reduction into 4 SMEM partial buffers.
// ---------------------------------------------------------------------------
__global__ void __launch_bounds__(1024) k_step_mma(int t) {
    if (t >= g_maxlen) return;
    int tile = blockIdx.x;
    int tid = threadIdx.x, w = tid >> 5, T = tid & 31;
    int gate = w & 3, kh = w >> 2;          // kh 0..7
    int rb = t & 1, wb = rb ^ 1;

    __shared__ float gsm[4][64 * 33];

    const uint4* Ap = (const uint4*)g_whh + (((size_t)tile * KC + kh * KH8) * 4 + gate) * 32 + T;
    const uint4* Bh = (const uint4*)g_hBhi[rb] + (size_t)kh * KH8 * 64 + T * 2;
    const uint4* Bl = (const uint4*)g_hBlo[rb] + (size_t)kh * KH8 * 64 + T * 2;

    float acc[4][4];
#pragma unroll
    for (int i = 0; i < 4; i++)
#pragma unroll
        for (int r = 0; r < 4; r++) acc[i][r] = 0.f;

    uint4 ah[2], bh[2][2], bl[2][2];
    ah[0] = Ap[0];
    bh[0][0] = Bh[0]; bh[0][1] = Bh[1];
    bl[0][0] = Bl[0]; bl[0][1] = Bl[1];

    for (int i = 0; i < KH8; i++) {
        int cur = i & 1, nxt = cur ^ 1;
        if (i + 1 < KH8) {
            ah[nxt] = Ap[(size_t)(i + 1) * 128];
            size_t bo = (size_t)(i + 1) * 64;
            bh[nxt][0] = Bh[bo];  bh[nxt][1] = Bh[bo + 1];
            bl[nxt][0] = Bl[bo];  bl[nxt][1] = Bl[bo + 1];
        }
        const uint32_t* Ar  = (const uint32_t*)&ah[cur];
        const uint32_t* Bhr = (const uint32_t*)&bh[cur][0];
        const uint32_t* Blr = (const uint32_t*)&bl[cur][0];
#pragma unroll
        for (int nt = 0; nt < 4; nt++) {
            mma16816h(acc[nt], Ar, Bhr + nt * 2);
            mma16816h(acc[nt], Ar, Blr + nt * 2);
        }
    }

    // two-phase partial reduce into 4 buffers: kh<4 store, then kh>=4 add
    if (kh < 4) {
#pragma unroll
        for (int nt = 0; nt < 4; nt++)
#pragma unroll
            for (int r = 0; r < 4; r++) {
                int rr = (T >> 2) + 8 * (r >> 1);
                int lane = nt * 8 + 2 * (T & 3) + (r & 1);
                gsm[kh][(gate * 16 + rr) * 33 + lane] = acc[nt][r];
            }
    }
    __syncthreads();
    if (kh >= 4) {
#pragma unroll
        for (int nt = 0; nt < 4; nt++)
#pragma unroll
            for (int r = 0; r < 4; r++) {
                int rr = (T >> 2) + 8 * (r >> 1);
                int lane = nt * 8 + 2 * (T & 3) + (r & 1);
                gsm[kh - 4][(gate * 16 + rr) * 33 + lane] += acc[nt][r];
            }
    }
    __syncthreads();

    // pointwise + repack h into fp16 B-fragment layout (256 thr = 32 lanes x 8 jp)
    if (tid < 256) {
        int lane = tid >> 3, jp = tid & 7;
        int jj0 = jp * 2;
        int Tt = (lane & 7) * 4 + ((jj0 & 7) >> 1);
        int nt = lane >> 3, b = jj0 >> 3;
        int idx = tile * 256 + Tt * 8 + nt * 2 + b;
        if (t < g_len[lane]) {
            float hv[2];
            const float* xp = g_xp + ((size_t)(lane * MAXS + t)) * GG;
#pragma unroll
            for (int q = 0; q < 2; q++) {
                int jj = jj0 + q;
                int j = tile * 16 + jj;
                float gi = gsm[0][(0 * 16 + jj) * 33 + lane] + gsm[1][(0 * 16 + jj) * 33 + lane]
                         + gsm[2][(0 * 16 + jj) * 33 + lane] + gsm[3][(0 * 16 + jj) * 33 + lane]
                         + xp[j];
                float gf = gsm[0][(1 * 16 + jj) * 33 + lane] + gsm[1][(1 * 16 + jj) * 33 + lane]
                         + gsm[2][(1 * 16 + jj) * 33 + lane] + gsm[3][(1 * 16 + jj) * 33 + lane]
                         + xp[HH + j];
                float gg = gsm[0][(2 * 16 + jj) * 33 + lane] + gsm[1][(2 * 16 + jj) * 33 + lane]
                         + gsm[2][(2 * 16 + jj) * 33 + lane] + gsm[3][(2 * 16 + jj) * 33 + lane]
                         + xp[2 * HH + j];
                float go = gsm[0][(3 * 16 + jj) * 33 + lane] + gsm[1][(3 * 16 + jj) * 33 + lane]
                         + gsm[2][(3 * 16 + jj) * 33 + lane] + gsm[3][(3 * 16 + jj) * 33 + lane]
                         + xp[3 * HH + j];
                size_t ci = (size_t)lane * HH + j;
                float cc = sigm(gf) * g_c[ci] + sigm(gi) * tanhf(gg);
                g_c[ci] = cc;
                float h = sigm(go) * tanhf(cc);
                g_h[ci] = h;
                hv[q] = h;
            }
            uint32_t h2, l2; split2h(hv[0], hv[1], h2, l2);
            g_hBhi[wb][idx] = h2;
            g_hBlo[wb][idx] = l2;
        } else {
            g_hBhi[wb][idx] = g_hBhi[rb][idx];
            g_hBlo[wb][idx] = g_hBlo[rb][idx];
        }
    }
}

// ---------------------------------------------------------------------------
// Kernel 6: out = [h_left ; h_right] @ W_out^T + b_out
// ---------------------------------------------------------------------------
__global__ void __launch_bounds__(256) k_out(const float* __restrict__ W_out,
                                             const float* __restrict__ b_out,
                                             float* __restrict__ out) {
    int e0 = blockIdx.x * 64;
    int tid = threadIdx.x;
    int eL = tid & 63;
    int bg = tid >> 6;

    __shared__ __align__(16) float Fs[32 * 16];
    __shared__ float Ws[64 * 33];
    float acc[4] = {0.f, 0.f, 0.f, 0.f};

    for (int k0 = 0; k0 < 2 * HH; k0 += 32) {
#pragma unroll
        for (int i = 0; i < 2; i++) {
            int flat = tid + i * 256;
            int b = flat & 15, k = flat >> 4;
            int kk = k0 + k;
            float v = (kk < HH) ? g_h[(size_t)b * HH + kk]
                                : g_h[(size_t)(BB + b) * HH + kk - HH];
            Fs[k * 16 + b] = v;
        }
#pragma unroll
        for (int i = 0; i < 8; i++) {
            int flat = tid + i * 256;
            int e = flat >> 5, k = flat & 31;
            Ws[e * 33 + k] = W_out[(size_t)(e0 + e) * (2 * HH) + k0 + k];
        }
        __syncthreads();
#pragma unroll
        for (int k = 0; k < 32; k++) {
            float wv = Ws[eL * 33 + k];
            float4 f = *(const float4*)&Fs[k * 16 + bg * 4];
            acc[0] += wv * f.x;  acc[1] += wv * f.y;
            acc[2] += wv * f.z;  acc[3] += wv * f.w;
        }
        __syncthreads();
    }
    int e = e0 + eL;
    float bo = b_out[e];
#pragma unroll
    for (int i = 0; i < 4; i++)
        out[(size_t)(bg * 4 + i) * EE + e] = acc[i] + bo;
}

// ---------------------------------------------------------------------------
extern "C" void kernel_launch(void* const* d_in, const int* in_sizes, int n_in,
                              void* d_out, int out_size) {
    const float* feat  = (const float*)d_in[0];
    const int*   mask  = (const int*)  d_in[1];
    const int*   start = (const int*)  d_in[2];
    const int*   end   = (const int*)  d_in[3];
    const float* W_ih  = (const float*)d_in[4];
    const float* W_hh  = (const float*)d_in[5];
    const float* b_ih  = (const float*)d_in[6];
    const float* b_hh  = (const float*)d_in[7];
    const float* W_out = (const float*)d_in[8];
    const float* b_out = (const float*)d_in[9];
    float* out = (float*)d_out;

    k_zero<<<72, 256>>>();
    k_prep<<<1, 512>>>(mask, start, end);
    k_whhprep<<<dim3(KC, NTH), 128>>>(W_hh);
    k_wihprep<<<dim3(KC, NXB), 128>>>(W_ih);
    k_aprep<<<dim3(9, 1024), 128>>>(feat, start, end);
    k_xp_mma<<<dim3(72, 8), 512>>>(b_ih, b_hh);
    for (int t = 0; t < NSTEPS; t++)
        k_step_mma<<<NTH, 1024>>>(t);
    k_out<<<EE / 64, 256>>>(W_out, b_out, out);
}

// round 16
// speedup vs baseline: 1.0393x; 1.0320x over previous
#include <cuda_runtime.h>
#include <cuda_fp16.h>
#include <math.h>
#include <stdint.h>

#define BB 16
#define TT 64
#define DD 2304
#define HH 2304
#define GG 9216
#define EE 768
#define LANES 32
#define MAXS 32
#define NSTEPS 31
#define KC 144            // K chunks of 16 (2304/16)
#define NTH 144           // step tiles: 16 j x 4 gates = 64 rows each
#define NXB 144           // W_ih blocks of 64 gate rows
#define KH4 36            // kc chunks per k-split quarter (144/4)

// ---------------- device scratch (no runtime allocation) --------------------
__device__ float g_xp [LANES * MAXS * GG];
__device__ float g_h[LANES * HH];            // final h per lane
__device__ float g_c[LANES * HH];
__device__ int   g_len[LANES];
__device__ int   g_length[BB];
__device__ int   g_maxlen;
__device__ int   g_nrows;
__device__ int   g_rows[1024];
// W_hh single-fp16 A-fragments: [tile(144)][kc(144)][gate(4)][T*4+a]  (u32 = 2 half)
__device__ uint32_t g_whh[NTH * KC * 4 * 128];
// W_ih single-fp16 B-fragments: [nblk(144)][kc(144)][T(32)][nt(8)*2+b]
__device__ uint32_t g_wih[NXB * KC * 32 * 16];
// seq rows fp16 hi/lo in A-fragment order: [mtile(16)][kc(144)][w4(4)][T*4+a]
__device__ uint32_t g_a_hi[16 * KC * 4 * 128], g_a_lo[16 * KC * 4 * 128];
// h fp16 hi/lo in B-fragment order, double buffered: [kc(144)][T(32)][nt(4)*2+b]
__device__ uint32_t g_hBhi[2][KC * 32 * 8], g_hBlo[2][KC * 32 * 8];

// ---------------- helpers ---------------------------------------------------
// fp16 pack (x -> low half)
__device__ __forceinline__ uint32_t packf16(float x, float y) {
    uint32_t h;
    asm("cvt.rn.f16x2.f32 %0, %1, %2;" : "=r"(h) : "f"(y), "f"(x));
    return h;
}
// fp16: split fp32 pair into packed f16x2 hi and lo
__device__ __forceinline__ void split2h(float x, float y, uint32_t& hi2, uint32_t& lo2) {
    uint32_t h = packf16(x, y);
    __half2 hh = *(__half2*)&h;
    float fx = __half2float(__low2half(hh));
    float fy = __half2float(__high2half(hh));
    lo2 = packf16(x - fx, y - fy);
    hi2 = h;
}
__device__ __forceinline__ void mma16816h(float* c, const uint32_t* a, const uint32_t* b) {
    asm volatile("mma.sync.aligned.m16n8k16.row.col.f32.f16.f16.f32 "
        "{%0,%1,%2,%3}, {%4,%5,%6,%7}, {%8,%9}, {%0,%1,%2,%3};"
        : "+f"(c[0]), "+f"(c[1]), "+f"(c[2]), "+f"(c[3])
        : "r"(a[0]), "r"(a[1]), "r"(a[2]), "r"(a[3]), "r"(b[0]), "r"(b[1]));
}
__device__ __forceinline__ float sigm(float x) { return 1.f / (1.f + expf(-x)); }

// ---------------------------------------------------------------------------
// Kernel 0a: zero states (parallel)
// ---------------------------------------------------------------------------
__global__ void k_zero() {
    int i = blockIdx.x * blockDim.x + threadIdx.x;
    int n = gridDim.x * blockDim.x;
    for (int p = i; p < LANES * HH; p += n) { g_h[p] = 0.f; g_c[p] = 0.f; }
    for (int p = i; p < KC * 32 * 8; p += n) { g_hBhi[0][p] = 0u; g_hBlo[0][p] = 0u; }
}

// ---------------------------------------------------------------------------
// Kernel 0b: lengths, compact row list
// ---------------------------------------------------------------------------
__global__ void k_prep(const int* __restrict__ mask,
                       const int* __restrict__ start,
                       const int* __restrict__ end) {
    int tid = threadIdx.x;
    __shared__ int s_len[LANES];
    if (tid < BB) {
        int L = 0;
        for (int t = 0; t < TT; t++) L += mask[tid * TT + t];
        g_length[tid] = L;
        int ll = start[tid] - 1; if (ll < 1) ll = 1;
        int rl = L - end[tid];   if (rl < 1) rl = 1;
        s_len[tid] = ll;  s_len[BB + tid] = rl;
        g_len[tid] = ll;  g_len[BB + tid] = rl;
    }
    __syncthreads();
    if (tid == 0) {
        int m = 0, n = 0;
        for (int lane = 0; lane < LANES; lane++) {
            int l = s_len[lane];
            if (l > m) m = l;
            for (int t = 0; t < l; t++) g_rows[n++] = (lane << 5) | t;
        }
        g_maxlen = m;
        g_nrows  = n;
    }
    __syncthreads();
    int nr = g_nrows;
    for (int m = nr + tid; m < 1024; m += blockDim.x) g_rows[m] = 0;
}

// ---------------------------------------------------------------------------
// Kernel 1: W_hh -> single-fp16 A-fragment order, coalesced writes.
// grid (KC, NTH), block 128: warp = gate, thread T writes uint4 (T*4+a)
// ---------------------------------------------------------------------------
__global__ void __launch_bounds__(128) k_whhprep(const float* __restrict__ W) {
    int kc = blockIdx.x, tile = blockIdx.y;
    int tid = threadIdx.x, gate = tid >> 5, T = tid & 31;
    uint32_t hi4[4];
#pragma unroll
    for (int a = 0; a < 4; a++) {
        int jj = (a & 1) * 8 + (T >> 2);
        int kk = (a >> 1) * 8 + (T & 3) * 2;
        int r = gate * HH + tile * 16 + jj;
        float2 v = *(const float2*)(W + (size_t)r * DD + kc * 16 + kk);
        hi4[a] = packf16(v.x, v.y);
    }
    size_t idx = (((size_t)tile * KC + kc) * 4 + gate) * 128 + T * 4;
    *(uint4*)&g_whh[idx] = *(uint4*)hi4;
}

// ---------------------------------------------------------------------------
// Kernel 2: W_ih -> single-fp16 B-fragment order, coalesced writes.
// ---------------------------------------------------------------------------
__global__ void __launch_bounds__(128) k_wihprep(const float* __restrict__ W) {
    int kc = blockIdx.x, nblk = blockIdx.y;
    int tid = threadIdx.x;
    int T = tid >> 2;
    uint32_t hi4[4];
#pragma unroll
    for (int i = 0; i < 4; i++) {
        int r = (tid & 3) * 4 + i;
        int nt = r >> 1, b = r & 1;
        int g = nblk * 64 + nt * 8 + (T >> 2);
        int kk = b * 8 + (T & 3) * 2;
        float2 v = *(const float2*)(W + (size_t)g * DD + kc * 16 + kk);
        hi4[i] = packf16(v.x, v.y);
    }
    size_t idx = ((size_t)nblk * KC + kc) * 512 + tid * 4;
    *(uint4*)&g_wih[idx] = *(uint4*)hi4;
}

// ---------------------------------------------------------------------------
// Kernel 3: fused gather + fp16 hi/lo fragment pack of compact seq rows
// ---------------------------------------------------------------------------
__global__ void k_aprep(const float* __restrict__ feat,
                        const int* __restrict__ start,
                        const int* __restrict__ end) {
    int m = blockIdx.y;
    int p = blockIdx.x * blockDim.x + threadIdx.x;
    int k = p * 2;
    int rc = g_rows[m];
    int lane = rc >> 5, t = rc & 31;
    const float* src = nullptr;
    if (lane < BB) {
        int b = lane;
        if (t + 1 < start[b]) src = feat + ((size_t)b * TT + (t + 1)) * DD;
    } else {
        int b = lane - BB;
        int raw = g_length[b] - end[b];
        if (t < raw) src = feat + ((size_t)b * TT + (end[b] + t)) * DD;
    }
    float2 v = make_float2(0.f, 0.f);
    if (src) v = *(const float2*)(src + k);
    int mtile = m >> 6, w = (m & 63) >> 4, rr = m & 15;
    int kc = k >> 4, kk = k & 15;
    int T = (rr & 7) * 4 + ((kk & 7) >> 1);
    int a = (rr >> 3) + 2 * (kk >> 3);
    uint32_t h2, l2; split2h(v.x, v.y, h2, l2);
    size_t idx = (((size_t)mtile * KC + kc) * 4 + w) * 128 + T * 4 + a;
    g_a_hi[idx] = h2;
    g_a_lo[idx] = l2;
}

// ---------------------------------------------------------------------------
// Kernel 4: xp GEMM, fp16 2-product, CTA tile M128 x N128, 512 thr (16 warps).
// grid (72, 8). #pragma unroll 4 forces cur/nxt static -> register promotion.
// ---------------------------------------------------------------------------
__global__ void __launch_bounds__(512) k_xp_mma(const float* __restrict__ b_ih,
                                                const float* __restrict__ b_hh) {
    int nrows = g_nrows;
    int m0 = blockIdx.y * 128;
    if (m0 >= nrows) return;
    int bx = blockIdx.x;
    int tid = threadIdx.x, w = tid >> 5, T = tid & 31;
    int mw = w >> 2, nw = w & 3;

    __shared__ int soff[128];
    if (tid < 128) {
        int rc = g_rows[m0 + tid];
        soff[tid] = ((rc >> 5) * MAXS + (rc & 31)) * GG;
    }
    __syncthreads();

    const uint4* Ah[2]; const uint4* Al[2];
#pragma unroll
    for (int mt = 0; mt < 2; mt++) {
        int g16 = mw * 2 + mt;
        int mtile = blockIdx.y * 2 + (g16 >> 2);
        int w4 = g16 & 3;
        Ah[mt] = (const uint4*)g_a_hi + (((size_t)mtile * KC) * 4 + w4) * 32 + T;
        Al[mt] = (const uint4*)g_a_lo + (((size_t)mtile * KC) * 4 + w4) * 32 + T;
    }
    int nblk = bx * 2 + (nw >> 1);
    const uint4* Bp = (const uint4*)g_wih + (((size_t)nblk * KC) * 32 + T) * 4 + (nw & 1) * 2;

    float acc[2][4][4];
#pragma unroll
    for (int mt = 0; mt < 2; mt++)
#pragma unroll
        for (int nt = 0; nt < 4; nt++)
#pragma unroll
            for (int r = 0; r < 4; r++) acc[mt][nt][r] = 0.f;

    uint4 ah[2][2], al[2][2], bp[2][2];
#pragma unroll
    for (int mt = 0; mt < 2; mt++) { ah[0][mt] = Ah[mt][0]; al[0][mt] = Al[mt][0]; }
    bp[0][0] = Bp[0]; bp[0][1] = Bp[1];

#pragma unroll 4
    for (int kc = 0; kc < KC; kc++) {
        int cur = kc & 1, nxt = cur ^ 1;
        if (kc + 1 < KC) {
            size_t o = (size_t)(kc + 1) * 128;
#pragma unroll
            for (int mt = 0; mt < 2; mt++) { ah[nxt][mt] = Ah[mt][o]; al[nxt][mt] = Al[mt][o]; }
            bp[nxt][0] = Bp[o]; bp[nxt][1] = Bp[o + 1];
        }
        const uint32_t* Br = (const uint32_t*)&bp[cur][0];
#pragma unroll
        for (int mt = 0; mt < 2; mt++) {
            const uint32_t* Ahr = (const uint32_t*)&ah[cur][mt];
            const uint32_t* Alr = (const uint32_t*)&al[cur][mt];
#pragma unroll
            for (int nt = 0; nt < 4; nt++) {
                mma16816h(acc[mt][nt], Ahr, Br + nt * 2);
                mma16816h(acc[mt][nt], Alr, Br + nt * 2);
            }
        }
    }

#pragma unroll
    for (int mt = 0; mt < 2; mt++)
#pragma unroll
        for (int nt = 0; nt < 4; nt++)
#pragma unroll
            for (int r = 0; r < 4; r++) {
                int g16 = mw * 2 + mt;
                int ml = g16 * 16 + (T >> 2) + 8 * (r >> 1);
                if (m0 + ml < nrows) {
                    int col = bx * 128 + (nw * 4 + nt) * 8 + 2 * (T & 3) + (r & 1);
                    g_xp[(size_t)soff[ml] + col] = acc[mt][nt][r] + b_ih[col] + b_hh[col];
                }
            }
}

// ---------------------------------------------------------------------------
// Kernel 5: one LSTM step via fp16 mma.sync, A single + B hi/lo (2 products).
// grid 144, block 512. warp = gate (w&3) x k-quarter (w>>2, 36 kc each).
// Fully unrolled mainloop -> double-buffer arrays promoted to registers.
// ---------------------------------------------------------------------------
__global__ void __launch_bounds__(512) k_step_mma(int t) {
    if (t >= g_maxlen) return;
    int tile = blockIdx.x;
    int tid = threadIdx.x, w = tid >> 5, T = tid & 31;
    int gate = w & 3, kh = w >> 2;          // kh 0..3
    int rb = t & 1, wb = rb ^ 1;

    __shared__ float gsm[4][64 * 33];

    const uint4* Ap = (const uint4*)g_whh + (((size_t)tile * KC + kh * KH4) * 4 + gate) * 32 + T;
    const uint4* Bh = (const uint4*)g_hBhi[rb] + (size_t)kh * KH4 * 64 + T * 2;
    const uint4* Bl = (const uint4*)g_hBlo[rb] + (size_t)kh * KH4 * 64 + T * 2;

    float acc[4][4];
#pragma unroll
    for (int i = 0; i < 4; i++)
#pragma unroll
        for (int r = 0; r < 4; r++) acc[i][r] = 0.f;

    uint4 ah[2], bh[2][2], bl[2][2];
    ah[0] = Ap[0];
    bh[0][0] = Bh[0]; bh[0][1] = Bh[1];
    bl[0][0] = Bl[0]; bl[0][1] = Bl[1];

#pragma unroll
    for (int i = 0; i < KH4; i++) {
        int cur = i & 1, nxt = cur ^ 1;
        if (i + 1 < KH4) {
            ah[nxt] = Ap[(size_t)(i + 1) * 128];
            size_t bo = (size_t)(i + 1) * 64;
            bh[nxt][0] = Bh[bo];  bh[nxt][1] = Bh[bo + 1];
            bl[nxt][0] = Bl[bo];  bl[nxt][1] = Bl[bo + 1];
        }
        const uint32_t* Ar  = (const uint32_t*)&ah[cur];
        const uint32_t* Bhr = (const uint32_t*)&bh[cur][0];
        const uint32_t* Blr = (const uint32_t*)&bl[cur][0];
#pragma unroll
        for (int nt = 0; nt < 4; nt++) {
            mma16816h(acc[nt], Ar, Bhr + nt * 2);
            mma16816h(acc[nt], Ar, Blr + nt * 2);
        }
    }

    // partial sums: warp (gate, kh) owns a disjoint 16x32 block of gsm[kh]
#pragma unroll
    for (int nt = 0; nt < 4; nt++)
#pragma unroll
        for (int r = 0; r < 4; r++) {
            int rr = (T >> 2) + 8 * (r >> 1);
            int lane = nt * 8 + 2 * (T & 3) + (r & 1);
            gsm[kh][(gate * 16 + rr) * 33 + lane] = acc[nt][r];
        }
    __syncthreads();

    // pointwise + repack h into fp16 B-fragment layout (256 thr = 32 lanes x 8 jp)
    if (tid < 256) {
        int lane = tid >> 3, jp = tid & 7;
        int jj0 = jp * 2;
        int Tt = (lane & 7) * 4 + ((jj0 & 7) >> 1);
        int nt = lane >> 3, b = jj0 >> 3;
        int idx = tile * 256 + Tt * 8 + nt * 2 + b;
        if (t < g_len[lane]) {
            float hv[2];
            const float* xp = g_xp + ((size_t)(lane * MAXS + t)) * GG;
#pragma unroll
            for (int q = 0; q < 2; q++) {
                int jj = jj0 + q;
                int j = tile * 16 + jj;
                float gi = gsm[0][(0 * 16 + jj) * 33 + lane] + gsm[1][(0 * 16 + jj) * 33 + lane]
                         + gsm[2][(0 * 16 + jj) * 33 + lane] + gsm[3][(0 * 16 + jj) * 33 + lane]
                         + xp[j];
                float gf = gsm[0][(1 * 16 + jj) * 33 + lane] + gsm[1][(1 * 16 + jj) * 33 + lane]
                         + gsm[2][(1 * 16 + jj) * 33 + lane] + gsm[3][(1 * 16 + jj) * 33 + lane]
                         + xp[HH + j];
                float gg = gsm[0][(2 * 16 + jj) * 33 + lane] + gsm[1][(2 * 16 + jj) * 33 + lane]
                         + gsm[2][(2 * 16 + jj) * 33 + lane] + gsm[3][(2 * 16 + jj) * 33 + lane]
                         + xp[2 * HH + j];
                float go = gsm[0][(3 * 16 + jj) * 33 + lane] + gsm[1][(3 * 16 + jj) * 33 + lane]
                         + gsm[2][(3 * 16 + jj) * 33 + lane] + gsm[3][(3 * 16 + jj) * 33 + lane]
                         + xp[3 * HH + j];
                size_t ci = (size_t)lane * HH + j;
                float cc = sigm(gf) * g_c[ci] + sigm(gi) * tanhf(gg);
                g_c[ci] = cc;
                float h = sigm(go) * tanhf(cc);
                g_h[ci] = h;
                hv[q] = h;
            }
            uint32_t h2, l2; split2h(hv[0], hv[1], h2, l2);
            g_hBhi[wb][idx] = h2;
            g_hBlo[wb][idx] = l2;
        } else {
            g_hBhi[wb][idx] = g_hBhi[rb][idx];
            g_hBlo[wb][idx] = g_hBlo[rb][idx];
        }
    }
}

// ---------------------------------------------------------------------------
// Kernel 6: out = [h_left ; h_right] @ W_out^T + b_out
// ---------------------------------------------------------------------------
__global__ void __launch_bounds__(256) k_out(const float* __restrict__ W_out,
                                             const float* __restrict__ b_out,
                                             float* __restrict__ out) {
    int e0 = blockIdx.x * 64;
    int tid = threadIdx.x;
    int eL = tid & 63;
    int bg = tid >> 6;

    __shared__ __align__(16) float Fs[32 * 16];
    __shared__ float Ws[64 * 33];
    float acc[4] = {0.f, 0.f, 0.f, 0.f};

    for (int k0 = 0; k0 < 2 * HH; k0 += 32) {
#pragma unroll
        for (int i = 0; i < 2; i++) {
            int flat = tid + i * 256;
            int b = flat & 15, k = flat >> 4;
            int kk = k0 + k;
            float v = (kk < HH) ? g_h[(size_t)b * HH + kk]
                                : g_h[(size_t)(BB + b) * HH + kk - HH];
            Fs[k * 16 + b] = v;
        }
#pragma unroll
        for (int i = 0; i < 8; i++) {
            int flat = tid + i * 256;
            int e = flat >> 5, k = flat & 31;
            Ws[e * 33 + k] = W_out[(size_t)(e0 + e) * (2 * HH) + k0 + k];
        }
        __syncthreads();
#pragma unroll
        for (int k = 0; k < 32; k++) {
            float wv = Ws[eL * 33 + k];
            float4 f = *(const float4*)&Fs[k * 16 + bg * 4];
            acc[0] += wv * f.x;  acc[1] += wv * f.y;
            acc[2] += wv * f.z;  acc[3] += wv * f.w;
        }
        __syncthreads();
    }
    int e = e0 + eL;
    float bo = b_out[e];
#pragma unroll
    for (int i = 0; i < 4; i++)
        out[(size_t)(bg * 4 + i) * EE + e] = acc[i] + bo;
}

// ---------------------------------------------------------------------------
extern "C" void kernel_launch(void* const* d_in, const int* in_sizes, int n_in,
                              void* d_out, int out_size) {
    const float* feat  = (const float*)d_in[0];
    const int*   mask  = (const int*)  d_in[1];
    const int*   start = (const int*)  d_in[2];
    const int*   end   = (const int*)  d_in[3];
    const float* W_ih  = (const float*)d_in[4];
    const float* W_hh  = (const float*)d_in[5];
    const float* b_ih  = (const float*)d_in[6];
    const float* b_hh  = (const float*)d_in[7];
    const float* W_out = (const float*)d_in[8];
    const float* b_out = (const float*)d_in[9];
    float* out = (float*)d_out;

    k_zero<<<72, 256>>>();
    k_prep<<<1, 512>>>(mask, start, end);
    k_whhprep<<<dim3(KC, NTH), 128>>>(W_hh);
    k_wihprep<<<dim3(KC, NXB), 128>>>(W_ih);
    k_aprep<<<dim3(9, 1024), 128>>>(feat, start, end);
    k_xp_mma<<<dim3(72, 8), 512>>>(b_ih, b_hh);
    for (int t = 0; t < NSTEPS; t++)
        k_step_mma<<<NTH, 512>>>(t);
    k_out<<<EE / 64, 256>>>(W_out, b_out, out);
}

// round 17
// speedup vs baseline: 1.2557x; 1.2082x over previous
#include <cuda_runtime.h>
#include <cuda_fp16.h>
#include <math.h>
#include <stdint.h>

#define BB 16
#define TT 64
#define DD 2304
#define HH 2304
#define GG 9216
#define EE 768
#define LANES 32
#define MAXS 32
#define NSTEPS 31
#define KC 144            // K chunks of 16 (2304/16)
#define NTH 144           // step tiles: 16 j x 4 gates = 64 rows each
#define NXB 144           // W_ih blocks of 64 gate rows
#define KH4 36            // kc chunks per k-split quarter (144/4)

// ---------------- device scratch (no runtime allocation) --------------------
__device__ float g_xp [LANES * MAXS * GG];
__device__ float g_h[LANES * HH];            // final h per lane (fp32)
__device__ float g_c[LANES * HH];
__device__ int   g_len[LANES];
__device__ int   g_length[BB];
__device__ int   g_maxlen;
__device__ int   g_nrows;
__device__ int   g_rows[1024];
// W_hh single-fp16 A-fragments: [tile(144)][kc(144)][gate(4)][T*4+a]  (u32 = 2 half)
__device__ uint32_t g_whh[NTH * KC * 4 * 128];
// W_ih single-fp16 B-fragments: [nblk(144)][kc(144)][T(32)][nt(8)*2+b]
__device__ uint32_t g_wih[NXB * KC * 32 * 16];
// seq rows fp16 hi/lo in A-fragment order: [mtile(16)][kc(144)][w4(4)][T*4+a]
__device__ uint32_t g_a_hi[16 * KC * 4 * 128], g_a_lo[16 * KC * 4 * 128];
// h single-fp16 in B-fragment order, double buffered: [kc(144)][T(32)][nt(4)*2+b]
__device__ uint32_t g_hB[2][KC * 32 * 8];

// ---------------- helpers ---------------------------------------------------
// fp16 pack (x -> low half)
__device__ __forceinline__ uint32_t packf16(float x, float y) {
    uint32_t h;
    asm("cvt.rn.f16x2.f32 %0, %1, %2;" : "=r"(h) : "f"(y), "f"(x));
    return h;
}
// fp16: split fp32 pair into packed f16x2 hi and lo
__device__ __forceinline__ void split2h(float x, float y, uint32_t& hi2, uint32_t& lo2) {
    uint32_t h = packf16(x, y);
    __half2 hh = *(__half2*)&h;
    float fx = __half2float(__low2half(hh));
    float fy = __half2float(__high2half(hh));
    lo2 = packf16(x - fx, y - fy);
    hi2 = h;
}
__device__ __forceinline__ void mma16816h(float* c, const uint32_t* a, const uint32_t* b) {
    asm volatile("mma.sync.aligned.m16n8k16.row.col.f32.f16.f16.f32 "
        "{%0,%1,%2,%3}, {%4,%5,%6,%7}, {%8,%9}, {%0,%1,%2,%3};"
        : "+f"(c[0]), "+f"(c[1]), "+f"(c[2]), "+f"(c[3])
        : "r"(a[0]), "r"(a[1]), "r"(a[2]), "r"(a[3]), "r"(b[0]), "r"(b[1]));
}
__device__ __forceinline__ float sigm(float x) { return 1.f / (1.f + expf(-x)); }

// ---------------------------------------------------------------------------
// Kernel 0a: zero states (parallel)
// ---------------------------------------------------------------------------
__global__ void k_zero() {
    int i = blockIdx.x * blockDim.x + threadIdx.x;
    int n = gridDim.x * blockDim.x;
    for (int p = i; p < LANES * HH; p += n) { g_h[p] = 0.f; g_c[p] = 0.f; }
    for (int p = i; p < KC * 32 * 8; p += n) g_hB[0][p] = 0u;
}

// ---------------------------------------------------------------------------
// Kernel 0b: lengths, compact row list
// ---------------------------------------------------------------------------
__global__ void k_prep(const int* __restrict__ mask,
                       const int* __restrict__ start,
                       const int* __restrict__ end) {
    int tid = threadIdx.x;
    __shared__ int s_len[LANES];
    if (tid < BB) {
        int L = 0;
        for (int t = 0; t < TT; t++) L += mask[tid * TT + t];
        g_length[tid] = L;
        int ll = start[tid] - 1; if (ll < 1) ll = 1;
        int rl = L - end[tid];   if (rl < 1) rl = 1;
        s_len[tid] = ll;  s_len[BB + tid] = rl;
        g_len[tid] = ll;  g_len[BB + tid] = rl;
    }
    __syncthreads();
    if (tid == 0) {
        int m = 0, n = 0;
        for (int lane = 0; lane < LANES; lane++) {
            int l = s_len[lane];
            if (l > m) m = l;
            for (int t = 0; t < l; t++) g_rows[n++] = (lane << 5) | t;
        }
        g_maxlen = m;
        g_nrows  = n;
    }
    __syncthreads();
    int nr = g_nrows;
    for (int m = nr + tid; m < 1024; m += blockDim.x) g_rows[m] = 0;
}

// ---------------------------------------------------------------------------
// Kernel 1: W_hh -> single-fp16 A-fragment order, coalesced writes.
// ---------------------------------------------------------------------------
__global__ void __launch_bounds__(128) k_whhprep(const float* __restrict__ W) {
    int kc = blockIdx.x, tile = blockIdx.y;
    int tid = threadIdx.x, gate = tid >> 5, T = tid & 31;
    uint32_t hi4[4];
#pragma unroll
    for (int a = 0; a < 4; a++) {
        int jj = (a & 1) * 8 + (T >> 2);
        int kk = (a >> 1) * 8 + (T & 3) * 2;
        int r = gate * HH + tile * 16 + jj;
        float2 v = *(const float2*)(W + (size_t)r * DD + kc * 16 + kk);
        hi4[a] = packf16(v.x, v.y);
    }
    size_t idx = (((size_t)tile * KC + kc) * 4 + gate) * 128 + T * 4;
    *(uint4*)&g_whh[idx] = *(uint4*)hi4;
}

// ---------------------------------------------------------------------------
// Kernel 2: W_ih -> single-fp16 B-fragment order, coalesced writes.
// ---------------------------------------------------------------------------
__global__ void __launch_bounds__(128) k_wihprep(const float* __restrict__ W) {
    int kc = blockIdx.x, nblk = blockIdx.y;
    int tid = threadIdx.x;
    int T = tid >> 2;
    uint32_t hi4[4];
#pragma unroll
    for (int i = 0; i < 4; i++) {
        int r = (tid & 3) * 4 + i;
        int nt = r >> 1, b = r & 1;
        int g = nblk * 64 + nt * 8 + (T >> 2);
        int kk = b * 8 + (T & 3) * 2;
        float2 v = *(const float2*)(W + (size_t)g * DD + kc * 16 + kk);
        hi4[i] = packf16(v.x, v.y);
    }
    size_t idx = ((size_t)nblk * KC + kc) * 512 + tid * 4;
    *(uint4*)&g_wih[idx] = *(uint4*)hi4;
}

// ---------------------------------------------------------------------------
// Kernel 3: fused gather + fp16 hi/lo fragment pack of compact seq rows
// ---------------------------------------------------------------------------
__global__ void k_aprep(const float* __restrict__ feat,
                        const int* __restrict__ start,
                        const int* __restrict__ end) {
    int m = blockIdx.y;
    int p = blockIdx.x * blockDim.x + threadIdx.x;
    int k = p * 2;
    int rc = g_rows[m];
    int lane = rc >> 5, t = rc & 31;
    const float* src = nullptr;
    if (lane < BB) {
        int b = lane;
        if (t + 1 < start[b]) src = feat + ((size_t)b * TT + (t + 1)) * DD;
    } else {
        int b = lane - BB;
        int raw = g_length[b] - end[b];
        if (t < raw) src = feat + ((size_t)b * TT + (end[b] + t)) * DD;
    }
    float2 v = make_float2(0.f, 0.f);
    if (src) v = *(const float2*)(src + k);
    int mtile = m >> 6, w = (m & 63) >> 4, rr = m & 15;
    int kc = k >> 4, kk = k & 15;
    int T = (rr & 7) * 4 + ((kk & 7) >> 1);
    int a = (rr >> 3) + 2 * (kk >> 3);
    uint32_t h2, l2; split2h(v.x, v.y, h2, l2);
    size_t idx = (((size_t)mtile * KC + kc) * 4 + w) * 128 + T * 4 + a;
    g_a_hi[idx] = h2;
    g_a_lo[idx] = l2;
}

// ---------------------------------------------------------------------------
// Kernel 4: xp GEMM, fp16 2-product, CTA tile M128 x N128, 512 thr (16 warps).
// grid (72, 8). (Unchanged from the 832us R15 configuration.)
// ---------------------------------------------------------------------------
__global__ void __launch_bounds__(512) k_xp_mma(const float* __restrict__ b_ih,
                                                const float* __restrict__ b_hh) {
    int nrows = g_nrows;
    int m0 = blockIdx.y * 128;
    if (m0 >= nrows) return;
    int bx = blockIdx.x;
    int tid = threadIdx.x, w = tid >> 5, T = tid & 31;
    int mw = w >> 2, nw = w & 3;

    __shared__ int soff[128];
    if (tid < 128) {
        int rc = g_rows[m0 + tid];
        soff[tid] = ((rc >> 5) * MAXS + (rc & 31)) * GG;
    }
    __syncthreads();

    const uint4* Ah[2]; const uint4* Al[2];
#pragma unroll
    for (int mt = 0; mt < 2; mt++) {
        int g16 = mw * 2 + mt;
        int mtile = blockIdx.y * 2 + (g16 >> 2);
        int w4 = g16 & 3;
        Ah[mt] = (const uint4*)g_a_hi + (((size_t)mtile * KC) * 4 + w4) * 32 + T;
        Al[mt] = (const uint4*)g_a_lo + (((size_t)mtile * KC) * 4 + w4) * 32 + T;
    }
    int nblk = bx * 2 + (nw >> 1);
    const uint4* Bp = (const uint4*)g_wih + (((size_t)nblk * KC) * 32 + T) * 4 + (nw & 1) * 2;

    float acc[2][4][4];
#pragma unroll
    for (int mt = 0; mt < 2; mt++)
#pragma unroll
        for (int nt = 0; nt < 4; nt++)
#pragma unroll
            for (int r = 0; r < 4; r++) acc[mt][nt][r] = 0.f;

    uint4 ah[2][2], al[2][2], bp[2][2];
#pragma unroll
    for (int mt = 0; mt < 2; mt++) { ah[0][mt] = Ah[mt][0]; al[0][mt] = Al[mt][0]; }
    bp[0][0] = Bp[0]; bp[0][1] = Bp[1];

#pragma unroll 4
    for (int kc = 0; kc < KC; kc++) {
        int cur = kc & 1, nxt = cur ^ 1;
        if (kc + 1 < KC) {
            size_t o = (size_t)(kc + 1) * 128;
#pragma unroll
            for (int mt = 0; mt < 2; mt++) { ah[nxt][mt] = Ah[mt][o]; al[nxt][mt] = Al[mt][o]; }
            bp[nxt][0] = Bp[o]; bp[nxt][1] = Bp[o + 1];
        }
        const uint32_t* Br = (const uint32_t*)&bp[cur][0];
#pragma unroll
        for (int mt = 0; mt < 2; mt++) {
            const uint32_t* Ahr = (const uint32_t*)&ah[cur][mt];
            const uint32_t* Alr = (const uint32_t*)&al[cur][mt];
#pragma unroll
            for (int nt = 0; nt < 4; nt++) {
                mma16816h(acc[mt][nt], Ahr, Br + nt * 2);
                mma16816h(acc[mt][nt], Alr, Br + nt * 2);
            }
        }
    }

#pragma unroll
    for (int mt = 0; mt < 2; mt++)
#pragma unroll
        for (int nt = 0; nt < 4; nt++)
#pragma unroll
            for (int r = 0; r < 4; r++) {
                int g16 = mw * 2 + mt;
                int ml = g16 * 16 + (T >> 2) + 8 * (r >> 1);
                if (m0 + ml < nrows) {
                    int col = bx * 128 + (nw * 4 + nt) * 8 + 2 * (T & 3) + (r & 1);
                    g_xp[(size_t)soff[ml] + col] = acc[mt][nt][r] + b_ih[col] + b_hh[col];
                }
            }
}

// ---------------------------------------------------------------------------
// Kernel 5: one LSTM step via fp16 mma.sync, A single + B single (1 product).
// grid 144, block 512. warp = gate (w&3) x k-quarter (w>>2, 36 kc each).
// ---------------------------------------------------------------------------
__global__ void __launch_bounds__(512) k_step_mma(int t) {
    if (t >= g_maxlen) return;
    int tile = blockIdx.x;
    int tid = threadIdx.x, w = tid >> 5, T = tid & 31;
    int gate = w & 3, kh = w >> 2;          // kh 0..3
    int rb = t & 1, wb = rb ^ 1;

    __shared__ float gsm[4][64 * 33];

    const uint4* Ap = (const uint4*)g_whh + (((size_t)tile * KC + kh * KH4) * 4 + gate) * 32 + T;
    const uint4* Bp = (const uint4*)g_hB[rb] + (size_t)kh * KH4 * 64 + T * 2;

    float acc[4][4];
#pragma unroll
    for (int i = 0; i < 4; i++)
#pragma unroll
        for (int r = 0; r < 4; r++) acc[i][r] = 0.f;

    uint4 ah[2], bp[2][2];
    ah[0] = Ap[0];
    bp[0][0] = Bp[0]; bp[0][1] = Bp[1];

#pragma unroll
    for (int i = 0; i < KH4; i++) {
        int cur = i & 1, nxt = cur ^ 1;
        if (i + 1 < KH4) {
            ah[nxt] = Ap[(size_t)(i + 1) * 128];
            size_t bo = (size_t)(i + 1) * 64;
            bp[nxt][0] = Bp[bo];  bp[nxt][1] = Bp[bo + 1];
        }
        const uint32_t* Ar = (const uint32_t*)&ah[cur];
        const uint32_t* Br = (const uint32_t*)&bp[cur][0];
#pragma unroll
        for (int nt = 0; nt < 4; nt++)
            mma16816h(acc[nt], Ar, Br + nt * 2);
    }

    // partial sums: warp (gate, kh) owns a disjoint 16x32 block of gsm[kh]
#pragma unroll
    for (int nt = 0; nt < 4; nt++)
#pragma unroll
        for (int r = 0; r < 4; r++) {
            int rr = (T >> 2) + 8 * (r >> 1);
            int lane = nt * 8 + 2 * (T & 3) + (r & 1);
            gsm[kh][(gate * 16 + rr) * 33 + lane] = acc[nt][r];
        }
    __syncthreads();

    // pointwise + repack h into fp16 B-fragment layout (256 thr = 32 lanes x 8 jp)
    if (tid < 256) {
        int lane = tid >> 3, jp = tid & 7;
        int jj0 = jp * 2;
        int Tt = (lane & 7) * 4 + ((jj0 & 7) >> 1);
        int nt = lane >> 3, b = jj0 >> 3;
        int idx = tile * 256 + Tt * 8 + nt * 2 + b;
        if (t < g_len[lane]) {
            float hv[2];
            const float* xp = g_xp + ((size_t)(lane * MAXS + t)) * GG;
#pragma unroll
            for (int q = 0; q < 2; q++) {
                int jj = jj0 + q;
                int j = tile * 16 + jj;
                float gi = gsm[0][(0 * 16 + jj) * 33 + lane] + gsm[1][(0 * 16 + jj) * 33 + lane]
                         + gsm[2][(0 * 16 + jj) * 33 + lane] + gsm[3][(0 * 16 + jj) * 33 + lane]
                         + xp[j];
                float gf = gsm[0][(1 * 16 + jj) * 33 + lane] + gsm[1][(1 * 16 + jj) * 33 + lane]
                         + gsm[2][(1 * 16 + jj) * 33 + lane] + gsm[3][(1 * 16 + jj) * 33 + lane]
                         + xp[HH + j];
                float gg = gsm[0][(2 * 16 + jj) * 33 + lane] + gsm[1][(2 * 16 + jj) * 33 + lane]
                         + gsm[2][(2 * 16 + jj) * 33 + lane] + gsm[3][(2 * 16 + jj) * 33 + lane]
                         + xp[2 * HH + j];
                float go = gsm[0][(3 * 16 + jj) * 33 + lane] + gsm[1][(3 * 16 + jj) * 33 + lane]
                         + gsm[2][(3 * 16 + jj) * 33 + lane] + gsm[3][(3 * 16 + jj) * 33 + lane]
                         + xp[3 * HH + j];
                size_t ci = (size_t)lane * HH + j;
                float cc = sigm(gf) * g_c[ci] + sigm(gi) * tanhf(gg);
                g_c[ci] = cc;
                float h = sigm(go) * tanhf(cc);
                g_h[ci] = h;
                hv[q] = h;
            }
            g_hB[wb][idx] = packf16(hv[0], hv[1]);
        } else {
            g_hB[wb][idx] = g_hB[rb][idx];
        }
    }
}

// ---------------------------------------------------------------------------
// Kernel 6: out = [h_left ; h_right] @ W_out^T + b_out
// ---------------------------------------------------------------------------
__global__ void __launch_bounds__(256) k_out(const float* __restrict__ W_out,
                                             const float* __restrict__ b_out,
                                             float* __restrict__ out) {
    int e0 = blockIdx.x * 64;
    int tid = threadIdx.x;
    int eL = tid & 63;
    int bg = tid >> 6;

    __shared__ __align__(16) float Fs[32 * 16];
    __shared__ float Ws[64 * 33];
    float acc[4] = {0.f, 0.f, 0.f, 0.f};

    for (int k0 = 0; k0 < 2 * HH; k0 += 32) {
#pragma unroll
        for (int i = 0; i < 2; i++) {
            int flat = tid + i * 256;
            int b = flat & 15, k = flat >> 4;
            int kk = k0 + k;
            float v = (kk < HH) ? g_h[(size_t)b * HH + kk]
                                : g_h[(size_t)(BB + b) * HH + kk - HH];
            Fs[k * 16 + b] = v;
        }
#pragma unroll
        for (int i = 0; i < 8; i++) {
            int flat = tid + i * 256;
            int e = flat >> 5, k = flat & 31;
            Ws[e * 33 + k] = W_out[(size_t)(e0 + e) * (2 * HH) + k0 + k];
        }
        __syncthreads();
#pragma unroll
        for (int k = 0; k < 32; k++) {
            float wv = Ws[eL * 33 + k];
            float4 f = *(const float4*)&Fs[k * 16 + bg * 4];
            acc[0] += wv * f.x;  acc[1] += wv * f.y;
            acc[2] += wv * f.z;  acc[3] += wv * f.w;
        }
        __syncthreads();
    }
    int e = e0 + eL;
    float bo = b_out[e];
#pragma unroll
    for (int i = 0; i < 4; i++)
        out[(size_t)(bg * 4 + i) * EE + e] = acc[i] + bo;
}

// ---------------------------------------------------------------------------
extern "C" void kernel_launch(void* const* d_in, const int* in_sizes, int n_in,
                              void* d_out, int out_size) {
    const float* feat  = (const float*)d_in[0];
    const int*   mask  = (const int*)  d_in[1];
    const int*   start = (const int*)  d_in[2];
    const int*   end   = (const int*)  d_in[3];
    const float* W_ih  = (const float*)d_in[4];
    const float* W_hh  = (const float*)d_in[5];
    const float* b_ih  = (const float*)d_in[6];
    const float* b_hh  = (const float*)d_in[7];
    const float* W_out = (const float*)d_in[8];
    const float* b_out = (const float*)d_in[9];
    float* out = (float*)d_out;

    k_zero<<<72, 256>>>();
    k_prep<<<1, 512>>>(mask, start, end);
    k_whhprep<<<dim3(KC, NTH), 128>>>(W_hh);
    k_wihprep<<<dim3(KC, NXB), 128>>>(W_ih);
    k_aprep<<<dim3(9, 1024), 128>>>(feat, start, end);
    k_xp_mma<<<dim3(72, 8), 512>>>(b_ih, b_hh);
    for (int t = 0; t < NSTEPS; t++)
        k_step_mma<<<NTH, 512>>>(t);
    k_out<<<EE / 64, 256>>>(W_out, b_out, out);
}